// round 2
// baseline (speedup 1.0000x reference)
#include <cuda_runtime.h>
#include <cuda_bf16.h>

#define SEQ 4096
#define DIM 1024
#define NH  16
#define HD  64

// Scratch for Q, K, V projections (16 MB each). __device__ globals are the
// sanctioned scratch mechanism (no allocations allowed).
__device__ float g_Q[SEQ * DIM];
__device__ float g_K[SEQ * DIM];
__device__ float g_V[SEQ * DIM];

// ---------------------------------------------------------------------------
// QKV projection: C = A(4096x1024) @ W(1024x1024) + bias
// Classic 128x128x8 SGEMM, 256 threads, 8x8 microtile (4+4 split columns/rows).
// blockIdx.z in {0,1,2} selects (Wq,bq)->g_Q, (Wk,bk)->g_K, (Wv,bv)->g_V.
// ---------------------------------------------------------------------------
__global__ __launch_bounds__(256) void qkv_gemm(
    const float* __restrict__ A,
    const float* __restrict__ Wq, const float* __restrict__ bq,
    const float* __restrict__ Wk, const float* __restrict__ bk,
    const float* __restrict__ Wv, const float* __restrict__ bv)
{
    const float* W;
    const float* bias;
    float* C;
    if (blockIdx.z == 0)      { W = Wq; bias = bq; C = g_Q; }
    else if (blockIdx.z == 1) { W = Wk; bias = bk; C = g_K; }
    else                      { W = Wv; bias = bv; C = g_V; }

    __shared__ float As[8][128];   // As[k][m]
    __shared__ float Ws[8][128];   // Ws[k][n]

    const int tid = threadIdx.x;
    const int m0 = blockIdx.y * 128;
    const int n0 = blockIdx.x * 128;

    // Load indices
    const int arow = tid >> 1;            // 0..127
    const int ak   = (tid & 1) * 4;       // 0 or 4
    const int wrow = tid >> 5;            // 0..7
    const int wc   = (tid & 31) * 4;      // 0..124

    // Compute microtile mapping: 4+4 split to reduce bank conflicts
    const int tma = (tid >> 4) * 4;       // 0..60 (row groups)
    const int tnb = (tid & 15) * 4;       // 0..60 (col groups)

    float acc[8][8];
#pragma unroll
    for (int i = 0; i < 8; i++)
#pragma unroll
        for (int j = 0; j < 8; j++) acc[i][j] = 0.f;

    for (int k0 = 0; k0 < DIM; k0 += 8) {
        // Load A tile (128 rows x 8 k), store transposed As[k][m]
        float4 av = *(const float4*)&A[(m0 + arow) * DIM + k0 + ak];
        As[ak + 0][arow] = av.x;
        As[ak + 1][arow] = av.y;
        As[ak + 2][arow] = av.z;
        As[ak + 3][arow] = av.w;
        // Load W tile (8 k x 128 n)
        *(float4*)&Ws[wrow][wc] = *(const float4*)&W[(k0 + wrow) * DIM + n0 + wc];
        __syncthreads();

#pragma unroll
        for (int k = 0; k < 8; k++) {
            float4 a0 = *(const float4*)&As[k][tma];
            float4 a1 = *(const float4*)&As[k][tma + 64];
            float4 b0 = *(const float4*)&Ws[k][tnb];
            float4 b1 = *(const float4*)&Ws[k][tnb + 64];
            float a[8] = {a0.x, a0.y, a0.z, a0.w, a1.x, a1.y, a1.z, a1.w};
            float b[8] = {b0.x, b0.y, b0.z, b0.w, b1.x, b1.y, b1.z, b1.w};
#pragma unroll
            for (int i = 0; i < 8; i++)
#pragma unroll
                for (int j = 0; j < 8; j++)
                    acc[i][j] = fmaf(a[i], b[j], acc[i][j]);
        }
        __syncthreads();
    }

    // Bias (preload per-thread columns)
    float bb[8];
#pragma unroll
    for (int j = 0; j < 4; j++) {
        bb[j]     = bias[n0 + tnb + j];
        bb[j + 4] = bias[n0 + 64 + tnb + j];
    }

#pragma unroll
    for (int i = 0; i < 8; i++) {
        int mi = m0 + ((i < 4) ? (tma + i) : (64 + tma + i - 4));
        float4 c0, c1;
        c0.x = acc[i][0] + bb[0];
        c0.y = acc[i][1] + bb[1];
        c0.z = acc[i][2] + bb[2];
        c0.w = acc[i][3] + bb[3];
        c1.x = acc[i][4] + bb[4];
        c1.y = acc[i][5] + bb[5];
        c1.z = acc[i][6] + bb[6];
        c1.w = acc[i][7] + bb[7];
        *(float4*)&C[mi * DIM + n0 + tnb]      = c0;
        *(float4*)&C[mi * DIM + n0 + 64 + tnb] = c1;
    }
}

// ---------------------------------------------------------------------------
// Flash-attention (fp32, online softmax).
// Grid: (SEQ/64, NH). Block: 256 threads.
// Each block: 64 query rows of one head. 4 threads per query row, each
// owning a 16-wide slice of head_dim. Scores staged in swizzled SMEM so
// register pressure stays low.
// ---------------------------------------------------------------------------
__global__ __launch_bounds__(256) void attn_kernel(float* __restrict__ out)
{
    __shared__ float Ks[64][64];
    __shared__ float Vs[64][64];
    __shared__ float Ss[64][64];   // swizzled columns: (j + 4*r) & 63

    const int tid = threadIdx.x;
    const int h = blockIdx.y;
    const int r = tid >> 2;        // query row within tile (0..63)
    const int quarter = tid & 3;   // which 16-wide head_dim slice
    const int row = blockIdx.x * 64 + r;
    const float scale = 0.125f;    // 1/sqrt(64)

    // Load this thread's Q slice (16 floats)
    float4 q4[4];
    {
        const float4* qp = (const float4*)&g_Q[row * DIM + h * HD + quarter * 16];
#pragma unroll
        for (int i = 0; i < 4; i++) q4[i] = qp[i];
    }

    float o[16];
#pragma unroll
    for (int i = 0; i < 16; i++) o[i] = 0.f;
    float m = -1e30f;
    float l = 0.f;

    for (int kt = 0; kt < SEQ / 64; kt++) {
        // Cooperative load of K,V tiles (64x64 floats each)
#pragma unroll
        for (int p = 0; p < 4; p++) {
            int lin = tid + p * 256;
            int rl = lin >> 4;
            int c4 = (lin & 15) * 4;
            int grow = kt * 64 + rl;
            *(float4*)&Ks[rl][c4] = *(const float4*)&g_K[grow * DIM + h * HD + c4];
            *(float4*)&Vs[rl][c4] = *(const float4*)&g_V[grow * DIM + h * HD + c4];
        }
        __syncthreads();

        // Scores: s[j] = scale * dot(q_row, K_j). Each thread computes a
        // 16-dim partial; quartet butterfly reduce gives the full dot.
        float mt = m;
#pragma unroll 8
        for (int j = 0; j < 64; j++) {
            float acc = 0.f;
#pragma unroll
            for (int d4 = 0; d4 < 4; d4++) {
                float4 kk = *(const float4*)&Ks[j][quarter * 16 + d4 * 4];
                acc = fmaf(q4[d4].x, kk.x, acc);
                acc = fmaf(q4[d4].y, kk.y, acc);
                acc = fmaf(q4[d4].z, kk.z, acc);
                acc = fmaf(q4[d4].w, kk.w, acc);
            }
            acc += __shfl_xor_sync(0xffffffffu, acc, 1);
            acc += __shfl_xor_sync(0xffffffffu, acc, 2);
            acc *= scale;
            if ((j & 3) == quarter) Ss[r][(j + 4 * r) & 63] = acc;
            mt = fmaxf(mt, acc);
        }

        // Online-softmax rescale
        float alpha = __expf(m - mt);
        m = mt;
        l *= alpha;
#pragma unroll
        for (int dd = 0; dd < 16; dd++) o[dd] *= alpha;

        __syncwarp();   // Ss writers/readers are the same quartet (same warp)

        // Accumulate P @ V
#pragma unroll 8
        for (int j = 0; j < 64; j++) {
            float p = __expf(Ss[r][(j + 4 * r) & 63] - m);
            l += p;
            const float4* vp = (const float4*)&Vs[j][quarter * 16];
#pragma unroll
            for (int d4 = 0; d4 < 4; d4++) {
                float4 vv = vp[d4];
                o[d4 * 4 + 0] = fmaf(p, vv.x, o[d4 * 4 + 0]);
                o[d4 * 4 + 1] = fmaf(p, vv.y, o[d4 * 4 + 1]);
                o[d4 * 4 + 2] = fmaf(p, vv.z, o[d4 * 4 + 2]);
                o[d4 * 4 + 3] = fmaf(p, vv.w, o[d4 * 4 + 3]);
            }
        }
        __syncthreads();
    }

    const float inv = 1.0f / l;
    float4 r0, r1, r2, r3;
    r0.x = o[0] * inv;  r0.y = o[1] * inv;  r0.z = o[2] * inv;  r0.w = o[3] * inv;
    r1.x = o[4] * inv;  r1.y = o[5] * inv;  r1.z = o[6] * inv;  r1.w = o[7] * inv;
    r2.x = o[8] * inv;  r2.y = o[9] * inv;  r2.z = o[10] * inv; r2.w = o[11] * inv;
    r3.x = o[12] * inv; r3.y = o[13] * inv; r3.z = o[14] * inv; r3.w = o[15] * inv;
    float4* op = (float4*)&out[row * DIM + h * HD + quarter * 16];
    op[0] = r0; op[1] = r1; op[2] = r2; op[3] = r3;
}

extern "C" void kernel_launch(void* const* d_in, const int* in_sizes, int n_in,
                              void* d_out, int out_size)
{
    const float* hs = (const float*)d_in[0];
    const float* Wq = (const float*)d_in[1];
    const float* bq = (const float*)d_in[2];
    const float* Wk = (const float*)d_in[3];
    const float* bk = (const float*)d_in[4];
    const float* Wv = (const float*)d_in[5];
    const float* bv = (const float*)d_in[6];
    float* out = (float*)d_out;

    dim3 g_gemm(DIM / 128, SEQ / 128, 3);
    qkv_gemm<<<g_gemm, 256>>>(hs, Wq, bq, Wk, bk, Wv, bv);

    dim3 g_attn(SEQ / 64, NH);
    attn_kernel<<<g_attn, 256>>>(out);
}

// round 4
// speedup vs baseline: 9.2515x; 9.2515x over previous
#include <cuda_runtime.h>
#include <cuda_bf16.h>
#include <cstdint>

#define SEQ 4096
#define DIM 1024
#define NH  16
#define HD  64

// Scratch for Q, K, V projections. __device__ globals = sanctioned scratch.
__device__ float g_Q[SEQ * DIM];
__device__ float g_K[SEQ * DIM];
__device__ float g_V[SEQ * DIM];

// ---------------------------------------------------------------------------
// helpers
// ---------------------------------------------------------------------------
__device__ __forceinline__ uint32_t f2tf32(float x) {
    uint32_t r;
    asm("cvt.rna.tf32.f32 %0, %1;" : "=r"(r) : "f"(x));
    return r;
}

__device__ __forceinline__ void mma_tf32(float* d, const uint32_t* a,
                                         uint32_t b0, uint32_t b1) {
    asm volatile(
        "mma.sync.aligned.m16n8k8.row.col.f32.tf32.tf32.f32 "
        "{%0,%1,%2,%3}, {%4,%5,%6,%7}, {%8,%9}, {%0,%1,%2,%3};\n"
        : "+f"(d[0]), "+f"(d[1]), "+f"(d[2]), "+f"(d[3])
        : "r"(a[0]), "r"(a[1]), "r"(a[2]), "r"(a[3]), "r"(b0), "r"(b1));
}

// ---------------------------------------------------------------------------
// QKV projection: C = A(4096x1024) @ W(1024x1024) + bias   (tf32 tensor cores)
// Block tile 128x128, K-step 32. 8 warps, warp tile 32x64.
// blockIdx.z selects Q/K/V.
// ---------------------------------------------------------------------------
#define AS_STRIDE 36    // floats; 4g+tig bank pattern -> conflict-free A frags
#define WS_STRIDE 136   // floats; 8*tig+g bank pattern -> conflict-free B frags

__global__ __launch_bounds__(256) void qkv_gemm_tf32(
    const float* __restrict__ A,
    const float* __restrict__ Wq, const float* __restrict__ bq,
    const float* __restrict__ Wk, const float* __restrict__ bk,
    const float* __restrict__ Wv, const float* __restrict__ bv)
{
    const float* W;
    const float* bias;
    float* C;
    if (blockIdx.z == 0)      { W = Wq; bias = bq; C = g_Q; }
    else if (blockIdx.z == 1) { W = Wk; bias = bk; C = g_K; }
    else                      { W = Wv; bias = bv; C = g_V; }

    __shared__ uint32_t As[128 * AS_STRIDE];  // [m][k] tf32
    __shared__ uint32_t Ws[32 * WS_STRIDE];   // [k][n] tf32

    const int tid  = threadIdx.x;
    const int lane = tid & 31;
    const int w    = tid >> 5;
    const int g    = lane >> 2;     // groupID
    const int tig  = lane & 3;      // thread-in-group
    const int wm   = (w & 3) * 32;  // warp row offset in tile
    const int wn   = (w >> 2) * 64; // warp col offset in tile

    const int m0 = blockIdx.y * 128;
    const int n0 = blockIdx.x * 128;

    float acc[2][8][4];
#pragma unroll
    for (int mi = 0; mi < 2; mi++)
#pragma unroll
        for (int ni = 0; ni < 8; ni++)
#pragma unroll
            for (int c = 0; c < 4; c++) acc[mi][ni][c] = 0.f;

    for (int k0 = 0; k0 < DIM; k0 += 32) {
        // stage A tile 128x32 (cvt to tf32)
#pragma unroll
        for (int it = 0; it < 4; it++) {
            int idx = tid + it * 256;
            int row = idx >> 3;
            int c4  = (idx & 7) * 4;
            float4 v = *(const float4*)&A[(m0 + row) * DIM + k0 + c4];
            uint32_t* dst = &As[row * AS_STRIDE + c4];
            dst[0] = f2tf32(v.x); dst[1] = f2tf32(v.y);
            dst[2] = f2tf32(v.z); dst[3] = f2tf32(v.w);
        }
        // stage W tile 32x128
#pragma unroll
        for (int it = 0; it < 4; it++) {
            int idx = tid + it * 256;
            int row = idx >> 5;
            int c4  = (idx & 31) * 4;
            float4 v = *(const float4*)&W[(k0 + row) * DIM + n0 + c4];
            uint32_t* dst = &Ws[row * WS_STRIDE + c4];
            dst[0] = f2tf32(v.x); dst[1] = f2tf32(v.y);
            dst[2] = f2tf32(v.z); dst[3] = f2tf32(v.w);
        }
        __syncthreads();

#pragma unroll
        for (int kk = 0; kk < 32; kk += 8) {
            uint32_t afr[2][4];
#pragma unroll
            for (int mi = 0; mi < 2; mi++) {
                int rb = wm + mi * 16;
                afr[mi][0] = As[(rb + g) * AS_STRIDE + kk + tig];
                afr[mi][1] = As[(rb + g + 8) * AS_STRIDE + kk + tig];
                afr[mi][2] = As[(rb + g) * AS_STRIDE + kk + tig + 4];
                afr[mi][3] = As[(rb + g + 8) * AS_STRIDE + kk + tig + 4];
            }
#pragma unroll
            for (int ni = 0; ni < 8; ni++) {
                int col = wn + ni * 8 + g;
                uint32_t b0 = Ws[(kk + tig) * WS_STRIDE + col];
                uint32_t b1 = Ws[(kk + tig + 4) * WS_STRIDE + col];
#pragma unroll
                for (int mi = 0; mi < 2; mi++)
                    mma_tf32(acc[mi][ni], afr[mi], b0, b1);
            }
        }
        __syncthreads();
    }

    // bias + store (float2 per row pair: cols 2*tig, 2*tig+1)
#pragma unroll
    for (int ni = 0; ni < 8; ni++) {
        int col = n0 + wn + ni * 8 + 2 * tig;
        float b0 = bias[col], b1 = bias[col + 1];
#pragma unroll
        for (int mi = 0; mi < 2; mi++) {
            int row = m0 + wm + mi * 16 + g;
            float2 v0 = make_float2(acc[mi][ni][0] + b0, acc[mi][ni][1] + b1);
            float2 v1 = make_float2(acc[mi][ni][2] + b0, acc[mi][ni][3] + b1);
            *(float2*)&C[row * DIM + col]       = v0;
            *(float2*)&C[(row + 8) * DIM + col] = v1;
        }
    }
}

// ---------------------------------------------------------------------------
// Flash attention on tf32 tensor cores.
// Grid (SEQ/128, NH). Block 256 = 8 warps; warp w owns Q rows w*16..w*16+15.
// KV tile = 64. S kept in mma C fragments; P converted C->A layout via
// intra-quad shuffles (no SMEM round-trip).
// ---------------------------------------------------------------------------
#define KV_STRIDE 68   // floats; conflict-free fragment reads, 16B-aligned rows

__global__ __launch_bounds__(256) void attn_tf32(float* __restrict__ out)
{
    __shared__ uint32_t Ks[64 * KV_STRIDE];  // K tile [j][k] tf32
    __shared__ uint32_t Vs[64 * KV_STRIDE];  // V tile [kv][d] tf32

    const int tid  = threadIdx.x;
    const int lane = tid & 31;
    const int w    = tid >> 5;
    const int g    = lane >> 2;
    const int tig  = lane & 3;
    const int h    = blockIdx.y;
    const int rowbase = blockIdx.x * 128 + w * 16;

    // Q fragments, pre-scaled by 1/sqrt(64)=0.125 (exact power of 2)
    uint32_t qa[8][4];
#pragma unroll
    for (int kf = 0; kf < 8; kf++) {
        const float* qp0 = &g_Q[(rowbase + g) * DIM + h * HD + kf * 8];
        const float* qp1 = &g_Q[(rowbase + g + 8) * DIM + h * HD + kf * 8];
        qa[kf][0] = f2tf32(qp0[tig] * 0.125f);
        qa[kf][1] = f2tf32(qp1[tig] * 0.125f);
        qa[kf][2] = f2tf32(qp0[tig + 4] * 0.125f);
        qa[kf][3] = f2tf32(qp1[tig + 4] * 0.125f);
    }

    float o[8][4];
#pragma unroll
    for (int nf = 0; nf < 8; nf++)
#pragma unroll
        for (int c = 0; c < 4; c++) o[nf][c] = 0.f;
    float m0_ = -1e30f, m1_ = -1e30f;   // running row max (rows g, g+8)
    float l0_ = 0.f,    l1_ = 0.f;      // running row sum

    for (int kt = 0; kt < SEQ / 64; kt++) {
        // stage K and V tiles (64x64), cvt to tf32
#pragma unroll
        for (int it = 0; it < 4; it++) {
            int idx = tid + it * 256;
            int row = idx >> 4;
            int c4  = (idx & 15) * 4;
            int grow = kt * 64 + row;
            float4 kv = *(const float4*)&g_K[grow * DIM + h * HD + c4];
            float4 vv = *(const float4*)&g_V[grow * DIM + h * HD + c4];
            uint32_t* kd = &Ks[row * KV_STRIDE + c4];
            uint32_t* vd = &Vs[row * KV_STRIDE + c4];
            kd[0] = f2tf32(kv.x); kd[1] = f2tf32(kv.y);
            kd[2] = f2tf32(kv.z); kd[3] = f2tf32(kv.w);
            vd[0] = f2tf32(vv.x); vd[1] = f2tf32(vv.y);
            vd[2] = f2tf32(vv.z); vd[3] = f2tf32(vv.w);
        }
        __syncthreads();

        // S = (Q*scale) @ K^T  : 8 n-frags (64 kv cols) x 8 k-frags
        float s[8][4];
#pragma unroll
        for (int nf = 0; nf < 8; nf++) {
            s[nf][0] = s[nf][1] = s[nf][2] = s[nf][3] = 0.f;
#pragma unroll
            for (int kf = 0; kf < 8; kf++) {
                uint32_t b0 = Ks[(nf * 8 + g) * KV_STRIDE + kf * 8 + tig];
                uint32_t b1 = Ks[(nf * 8 + g) * KV_STRIDE + kf * 8 + tig + 4];
                mma_tf32(s[nf], qa[kf], b0, b1);
            }
        }

        // online softmax: row max over quad
        float mx0 = -1e30f, mx1 = -1e30f;
#pragma unroll
        for (int nf = 0; nf < 8; nf++) {
            mx0 = fmaxf(mx0, fmaxf(s[nf][0], s[nf][1]));
            mx1 = fmaxf(mx1, fmaxf(s[nf][2], s[nf][3]));
        }
        mx0 = fmaxf(mx0, __shfl_xor_sync(0xffffffffu, mx0, 1));
        mx0 = fmaxf(mx0, __shfl_xor_sync(0xffffffffu, mx0, 2));
        mx1 = fmaxf(mx1, __shfl_xor_sync(0xffffffffu, mx1, 1));
        mx1 = fmaxf(mx1, __shfl_xor_sync(0xffffffffu, mx1, 2));
        float mn0 = fmaxf(m0_, mx0);
        float mn1 = fmaxf(m1_, mx1);
        float a0 = __expf(m0_ - mn0);
        float a1 = __expf(m1_ - mn1);
        m0_ = mn0; m1_ = mn1;
        l0_ *= a0; l1_ *= a1;
#pragma unroll
        for (int nf = 0; nf < 8; nf++) {
            o[nf][0] *= a0; o[nf][1] *= a0;
            o[nf][2] *= a1; o[nf][3] *= a1;
        }

        // probabilities + row sums
        float rs0 = 0.f, rs1 = 0.f;
#pragma unroll
        for (int nf = 0; nf < 8; nf++) {
            s[nf][0] = __expf(s[nf][0] - mn0);
            s[nf][1] = __expf(s[nf][1] - mn0);
            s[nf][2] = __expf(s[nf][2] - mn1);
            s[nf][3] = __expf(s[nf][3] - mn1);
            rs0 += s[nf][0] + s[nf][1];
            rs1 += s[nf][2] + s[nf][3];
        }
        rs0 += __shfl_xor_sync(0xffffffffu, rs0, 1);
        rs0 += __shfl_xor_sync(0xffffffffu, rs0, 2);
        rs1 += __shfl_xor_sync(0xffffffffu, rs1, 1);
        rs1 += __shfl_xor_sync(0xffffffffu, rs1, 2);
        l0_ += rs0; l1_ += rs1;

        // O += P @ V : convert C-frag -> A-frag with intra-quad shuffles.
        // C frag: lane (g,q) holds cols {2q,2q+1}; A frag needs cols {tig,tig+4}.
        const int srcA = g * 4 + (tig >> 1);
        const int srcB = srcA + 2;
        const bool odd = (tig & 1);
#pragma unroll
        for (int kf = 0; kf < 8; kf++) {
            float v00 = __shfl_sync(0xffffffffu, s[kf][0], srcA);
            float v01 = __shfl_sync(0xffffffffu, s[kf][1], srcA);
            float v20 = __shfl_sync(0xffffffffu, s[kf][0], srcB);
            float v21 = __shfl_sync(0xffffffffu, s[kf][1], srcB);
            float v10 = __shfl_sync(0xffffffffu, s[kf][2], srcA);
            float v11 = __shfl_sync(0xffffffffu, s[kf][3], srcA);
            float v30 = __shfl_sync(0xffffffffu, s[kf][2], srcB);
            float v31 = __shfl_sync(0xffffffffu, s[kf][3], srcB);
            uint32_t pa[4];
            pa[0] = f2tf32(odd ? v01 : v00);
            pa[1] = f2tf32(odd ? v11 : v10);
            pa[2] = f2tf32(odd ? v21 : v20);
            pa[3] = f2tf32(odd ? v31 : v30);
#pragma unroll
            for (int nf = 0; nf < 8; nf++) {
                uint32_t b0 = Vs[(kf * 8 + tig) * KV_STRIDE + nf * 8 + g];
                uint32_t b1 = Vs[(kf * 8 + tig + 4) * KV_STRIDE + nf * 8 + g];
                mma_tf32(o[nf], pa, b0, b1);
            }
        }
        __syncthreads();
    }

    // normalize + store (float2: cols 2*tig, 2*tig+1)
    float inv0 = 1.0f / l0_;
    float inv1 = 1.0f / l1_;
#pragma unroll
    for (int nf = 0; nf < 8; nf++) {
        int col = h * HD + nf * 8 + 2 * tig;
        float2 v0 = make_float2(o[nf][0] * inv0, o[nf][1] * inv0);
        float2 v1 = make_float2(o[nf][2] * inv1, o[nf][3] * inv1);
        *(float2*)&out[(rowbase + g) * DIM + col]     = v0;
        *(float2*)&out[(rowbase + g + 8) * DIM + col] = v1;
    }
}

extern "C" void kernel_launch(void* const* d_in, const int* in_sizes, int n_in,
                              void* d_out, int out_size)
{
    const float* hs = (const float*)d_in[0];
    const float* Wq = (const float*)d_in[1];
    const float* bq = (const float*)d_in[2];
    const float* Wk = (const float*)d_in[3];
    const float* bk = (const float*)d_in[4];
    const float* Wv = (const float*)d_in[5];
    const float* bv = (const float*)d_in[6];
    float* out = (float*)d_out;

    dim3 g_gemm(DIM / 128, SEQ / 128, 3);
    qkv_gemm_tf32<<<g_gemm, 256>>>(hs, Wq, bq, Wk, bk, Wv, bv);

    dim3 g_attn(SEQ / 128, NH);
    attn_tf32<<<g_attn, 256>>>(out);
}

// round 6
// speedup vs baseline: 10.3593x; 1.1197x over previous
#include <cuda_runtime.h>
#include <cuda_bf16.h>
#include <cstdint>

#define SEQ 4096
#define DIM 1024
#define NH  16
#define HD  64

// Scratch for Q, K, V projections. __device__ globals = sanctioned scratch.
__device__ float g_Q[SEQ * DIM];
__device__ float g_K[SEQ * DIM];
__device__ float g_V[SEQ * DIM];

// ---------------------------------------------------------------------------
// helpers
// ---------------------------------------------------------------------------
__device__ __forceinline__ uint32_t f2tf32(float x) {
    uint32_t r;
    asm("cvt.rna.tf32.f32 %0, %1;" : "=r"(r) : "f"(x));
    return r;
}

__device__ __forceinline__ float ex2f(float x) {
    float r;
    asm("ex2.approx.ftz.f32 %0, %1;" : "=f"(r) : "f"(x));
    return r;
}

__device__ __forceinline__ void mma_tf32(float* d, const uint32_t* a,
                                         uint32_t b0, uint32_t b1) {
    asm volatile(
        "mma.sync.aligned.m16n8k8.row.col.f32.tf32.tf32.f32 "
        "{%0,%1,%2,%3}, {%4,%5,%6,%7}, {%8,%9}, {%0,%1,%2,%3};\n"
        : "+f"(d[0]), "+f"(d[1]), "+f"(d[2]), "+f"(d[3])
        : "r"(a[0]), "r"(a[1]), "r"(a[2]), "r"(a[3]), "r"(b0), "r"(b1));
}

__device__ __forceinline__ void ldsm_x4(uint32_t& r0, uint32_t& r1,
                                        uint32_t& r2, uint32_t& r3,
                                        uint32_t addr) {
    asm volatile(
        "ldmatrix.sync.aligned.m8n8.x4.shared.b16 {%0,%1,%2,%3}, [%4];"
        : "=r"(r0), "=r"(r1), "=r"(r2), "=r"(r3) : "r"(addr));
}

// ---------------------------------------------------------------------------
// QKV projection: C = A(4096x1024) @ W(1024x1024) + bias   (tf32 tensor cores)
// Block tile 128x128, K-step 32. 8 warps, warp tile 32x64.
// ---------------------------------------------------------------------------
#define AS_STRIDE 36
#define WS_STRIDE 136

__global__ __launch_bounds__(256) void qkv_gemm_tf32(
    const float* __restrict__ A,
    const float* __restrict__ Wq, const float* __restrict__ bq,
    const float* __restrict__ Wk, const float* __restrict__ bk,
    const float* __restrict__ Wv, const float* __restrict__ bv)
{
    const float* W;
    const float* bias;
    float* C;
    if (blockIdx.z == 0)      { W = Wq; bias = bq; C = g_Q; }
    else if (blockIdx.z == 1) { W = Wk; bias = bk; C = g_K; }
    else                      { W = Wv; bias = bv; C = g_V; }

    __shared__ uint32_t As[128 * AS_STRIDE];
    __shared__ uint32_t Ws[32 * WS_STRIDE];

    const int tid  = threadIdx.x;
    const int lane = tid & 31;
    const int w    = tid >> 5;
    const int g    = lane >> 2;
    const int tig  = lane & 3;
    const int wm   = (w & 3) * 32;
    const int wn   = (w >> 2) * 64;

    const int m0 = blockIdx.y * 128;
    const int n0 = blockIdx.x * 128;

    float acc[2][8][4];
#pragma unroll
    for (int mi = 0; mi < 2; mi++)
#pragma unroll
        for (int ni = 0; ni < 8; ni++)
#pragma unroll
            for (int c = 0; c < 4; c++) acc[mi][ni][c] = 0.f;

    for (int k0 = 0; k0 < DIM; k0 += 32) {
#pragma unroll
        for (int it = 0; it < 4; it++) {
            int idx = tid + it * 256;
            int row = idx >> 3;
            int c4  = (idx & 7) * 4;
            float4 v = *(const float4*)&A[(m0 + row) * DIM + k0 + c4];
            uint32_t* dst = &As[row * AS_STRIDE + c4];
            dst[0] = f2tf32(v.x); dst[1] = f2tf32(v.y);
            dst[2] = f2tf32(v.z); dst[3] = f2tf32(v.w);
        }
#pragma unroll
        for (int it = 0; it < 4; it++) {
            int idx = tid + it * 256;
            int row = idx >> 5;
            int c4  = (idx & 31) * 4;
            float4 v = *(const float4*)&W[(k0 + row) * DIM + n0 + c4];
            uint32_t* dst = &Ws[row * WS_STRIDE + c4];
            dst[0] = f2tf32(v.x); dst[1] = f2tf32(v.y);
            dst[2] = f2tf32(v.z); dst[3] = f2tf32(v.w);
        }
        __syncthreads();

#pragma unroll
        for (int kk = 0; kk < 32; kk += 8) {
            uint32_t afr[2][4];
#pragma unroll
            for (int mi = 0; mi < 2; mi++) {
                int rb = wm + mi * 16;
                afr[mi][0] = As[(rb + g) * AS_STRIDE + kk + tig];
                afr[mi][1] = As[(rb + g + 8) * AS_STRIDE + kk + tig];
                afr[mi][2] = As[(rb + g) * AS_STRIDE + kk + tig + 4];
                afr[mi][3] = As[(rb + g + 8) * AS_STRIDE + kk + tig + 4];
            }
#pragma unroll
            for (int ni = 0; ni < 8; ni++) {
                int col = wn + ni * 8 + g;
                uint32_t b0 = Ws[(kk + tig) * WS_STRIDE + col];
                uint32_t b1 = Ws[(kk + tig + 4) * WS_STRIDE + col];
#pragma unroll
                for (int mi = 0; mi < 2; mi++)
                    mma_tf32(acc[mi][ni], afr[mi], b0, b1);
            }
        }
        __syncthreads();
    }

#pragma unroll
    for (int ni = 0; ni < 8; ni++) {
        int col = n0 + wn + ni * 8 + 2 * tig;
        float b0 = bias[col], b1 = bias[col + 1];
#pragma unroll
        for (int mi = 0; mi < 2; mi++) {
            int row = m0 + wm + mi * 16 + g;
            float2 v0 = make_float2(acc[mi][ni][0] + b0, acc[mi][ni][1] + b1);
            float2 v1 = make_float2(acc[mi][ni][2] + b0, acc[mi][ni][3] + b1);
            *(float2*)&C[row * DIM + col]       = v0;
            *(float2*)&C[(row + 8) * DIM + col] = v1;
        }
    }
}

// ---------------------------------------------------------------------------
// Flash attention, tf32 tensor cores, ldmatrix fragments, shuffle-free PV.
//
// Grid (SEQ/128, NH), block 256 = 8 warps; warp w owns Q rows w*16..+15.
// KV tile 64. K stored [kv][d] (row stride 68). V stored TRANSPOSED
// [d][kv_perm] with kv interleaved within each 8-block:
//     pos(kv) = (kv&1)*4 + ((kv>>1)&3)
// so the S C-fragment (cols 2*tig, 2*tig+1) feeds the PV mma A slot directly
// (mma is invariant under a consistent permutation of the k index).
// Vt columns additionally XOR-swizzled in 16B units by (d>>3)&7 to keep the
// transpose staging writes nearly conflict-free.
// ---------------------------------------------------------------------------
#define KV_STRIDE 68

__global__ __launch_bounds__(256) void attn_tf32(float* __restrict__ out)
{
    __shared__ uint32_t Ks[64 * KV_STRIDE];   // [kv][d] tf32
    __shared__ uint32_t Vt[64 * KV_STRIDE];   // [d][kv_perm^swz] tf32

    const int tid  = threadIdx.x;
    const int lane = tid & 31;
    const int w    = tid >> 5;
    const int g    = lane >> 2;
    const int tig  = lane & 3;
    const int h    = blockIdx.y;
    const int rowbase = blockIdx.x * 128 + w * 16;

    const uint32_t ks_base = (uint32_t)__cvta_generic_to_shared(Ks);
    const uint32_t vt_base = (uint32_t)__cvta_generic_to_shared(Vt);

    // ldmatrix per-lane row/col components (shared by K and Vt addressing)
    const int lrow = lane & 7;        // row within 8-row tile
    const int lmat = lane >> 3;       // which of the 4 matrices

    // Q fragments, pre-scaled by 0.125 * log2(e) (base-2 softmax)
    const float qscale = 0.125f * 1.4426950408889634f;
    uint32_t qa[8][4];
#pragma unroll
    for (int kf = 0; kf < 8; kf++) {
        const float* qp0 = &g_Q[(rowbase + g) * DIM + h * HD + kf * 8];
        const float* qp1 = &g_Q[(rowbase + g + 8) * DIM + h * HD + kf * 8];
        qa[kf][0] = f2tf32(qp0[tig] * qscale);
        qa[kf][1] = f2tf32(qp1[tig] * qscale);
        qa[kf][2] = f2tf32(qp0[tig + 4] * qscale);
        qa[kf][3] = f2tf32(qp1[tig + 4] * qscale);
    }

    float o[8][4];
#pragma unroll
    for (int nf = 0; nf < 8; nf++)
#pragma unroll
        for (int c = 0; c < 4; c++) o[nf][c] = 0.f;
    float m0_ = -1e30f, m1_ = -1e30f;
    float l0_ = 0.f,    l1_ = 0.f;

    for (int kt = 0; kt < SEQ / 64; kt++) {
        // ---- stage K [kv][d] and V^T (permuted+swizzled) ----
#pragma unroll
        for (int it = 0; it < 4; it++) {
            int idx = tid + it * 256;
            int kv  = idx >> 4;             // 0..63
            int c4  = (idx & 15) * 4;       // d base
            int grow = kt * 64 + kv;
            float4 kk = *(const float4*)&g_K[grow * DIM + h * HD + c4];
            float4 vv = *(const float4*)&g_V[grow * DIM + h * HD + c4];
            uint32_t* kd = &Ks[kv * KV_STRIDE + c4];
            kd[0] = f2tf32(kk.x); kd[1] = f2tf32(kk.y);
            kd[2] = f2tf32(kk.z); kd[3] = f2tf32(kk.w);
            // V transpose: kv -> interleaved pos within its 8-block
            int kvp = (kv & ~7) | (((kv & 1) << 2) | ((kv >> 1) & 3));
            int u   = kvp >> 2;
            int wi  = kvp & 3;
            float vvf[4] = {vv.x, vv.y, vv.z, vv.w};
#pragma unroll
            for (int i = 0; i < 4; i++) {
                int d = c4 + i;
                Vt[d * KV_STRIDE + 4 * (u ^ ((d >> 3) & 7)) + wi] = f2tf32(vvf[i]);
            }
        }
        __syncthreads();

        // ---- S = (Q*qscale) @ K^T via ldmatrix.x4 ----
        float s[8][4];
#pragma unroll
        for (int nf = 0; nf < 8; nf++) {
            s[nf][0] = s[nf][1] = s[nf][2] = s[nf][3] = 0.f;
            int krow = nf * 8 + lrow;
#pragma unroll
            for (int kfp = 0; kfp < 4; kfp++) {
                // matrices: (kf,b0),(kf,b1),(kf+1,b0),(kf+1,b1), kf=2*kfp
                uint32_t addr = ks_base +
                    (uint32_t)(krow * KV_STRIDE + kfp * 16 + lmat * 4) * 4u;
                uint32_t b00, b01, b10, b11;
                ldsm_x4(b00, b01, b10, b11, addr);
                mma_tf32(s[nf], qa[2 * kfp],     b00, b01);
                mma_tf32(s[nf], qa[2 * kfp + 1], b10, b11);
            }
        }

        // ---- online softmax (base 2) ----
        float mx0 = -1e30f, mx1 = -1e30f;
#pragma unroll
        for (int nf = 0; nf < 8; nf++) {
            mx0 = fmaxf(mx0, fmaxf(s[nf][0], s[nf][1]));
            mx1 = fmaxf(mx1, fmaxf(s[nf][2], s[nf][3]));
        }
        mx0 = fmaxf(mx0, __shfl_xor_sync(0xffffffffu, mx0, 1));
        mx0 = fmaxf(mx0, __shfl_xor_sync(0xffffffffu, mx0, 2));
        mx1 = fmaxf(mx1, __shfl_xor_sync(0xffffffffu, mx1, 1));
        mx1 = fmaxf(mx1, __shfl_xor_sync(0xffffffffu, mx1, 2));
        float mn0 = fmaxf(m0_, mx0);
        float mn1 = fmaxf(m1_, mx1);
        float a0 = ex2f(m0_ - mn0);
        float a1 = ex2f(m1_ - mn1);
        m0_ = mn0; m1_ = mn1;
        l0_ *= a0; l1_ *= a1;
#pragma unroll
        for (int nf = 0; nf < 8; nf++) {
            o[nf][0] *= a0; o[nf][1] *= a0;
            o[nf][2] *= a1; o[nf][3] *= a1;
        }

        // ---- probabilities, row sums, pack straight into PV A-fragments ----
        // A-frag (permuted k): {row g col 2tig, row g+8 col 2tig,
        //                       row g col 2tig+1, row g+8 col 2tig+1}
        float rs0 = 0.f, rs1 = 0.f;
        uint32_t p[8][4];
#pragma unroll
        for (int nf = 0; nf < 8; nf++) {
            float e0 = ex2f(s[nf][0] - mn0);
            float e1 = ex2f(s[nf][1] - mn0);
            float e2 = ex2f(s[nf][2] - mn1);
            float e3 = ex2f(s[nf][3] - mn1);
            rs0 += e0 + e1;
            rs1 += e2 + e3;
            p[nf][0] = f2tf32(e0);
            p[nf][1] = f2tf32(e2);
            p[nf][2] = f2tf32(e1);
            p[nf][3] = f2tf32(e3);
        }
        rs0 += __shfl_xor_sync(0xffffffffu, rs0, 1);
        rs0 += __shfl_xor_sync(0xffffffffu, rs0, 2);
        rs1 += __shfl_xor_sync(0xffffffffu, rs1, 1);
        rs1 += __shfl_xor_sync(0xffffffffu, rs1, 2);
        l0_ += rs0; l1_ += rs1;

        // ---- O += P @ V via ldmatrix.x4 on transposed/permuted V ----
#pragma unroll
        for (int nf = 0; nf < 8; nf++) {
            int d = nf * 8 + lrow;
            int swz = (d >> 3) & 7;      // == nf
#pragma unroll
            for (int kfp = 0; kfp < 4; kfp++) {
                int ulog = 4 * kfp + lmat;   // 2*kf + m, kf = 2*kfp
                uint32_t addr = vt_base +
                    (uint32_t)(d * KV_STRIDE + 4 * (ulog ^ swz)) * 4u;
                uint32_t v0, v1, v2, v3;
                ldsm_x4(v0, v1, v2, v3, addr);
                mma_tf32(o[nf], p[2 * kfp],     v0, v1);
                mma_tf32(o[nf], p[2 * kfp + 1], v2, v3);
            }
        }
        __syncthreads();
    }

    // ---- normalize + store ----
    float inv0 = 1.0f / l0_;
    float inv1 = 1.0f / l1_;
#pragma unroll
    for (int nf = 0; nf < 8; nf++) {
        int col = h * HD + nf * 8 + 2 * tig;
        float2 v0 = make_float2(o[nf][0] * inv0, o[nf][1] * inv0);
        float2 v1 = make_float2(o[nf][2] * inv1, o[nf][3] * inv1);
        *(float2*)&out[(rowbase + g) * DIM + col]     = v0;
        *(float2*)&out[(rowbase + g + 8) * DIM + col] = v1;
    }
}

extern "C" void kernel_launch(void* const* d_in, const int* in_sizes, int n_in,
                              void* d_out, int out_size)
{
    const float* hs = (const float*)d_in[0];
    const float* Wq = (const float*)d_in[1];
    const float* bq = (const float*)d_in[2];
    const float* Wk = (const float*)d_in[3];
    const float* bk = (const float*)d_in[4];
    const float* Wv = (const float*)d_in[5];
    const float* bv = (const float*)d_in[6];
    float* out = (float*)d_out;

    dim3 g_gemm(DIM / 128, SEQ / 128, 3);
    qkv_gemm_tf32<<<g_gemm, 256>>>(hs, Wq, bq, Wk, bk, Wv, bv);

    dim3 g_attn(SEQ / 128, NH);
    attn_tf32<<<g_attn, 256>>>(out);
}

// round 7
// speedup vs baseline: 13.3139x; 1.2852x over previous
#include <cuda_runtime.h>
#include <cuda_bf16.h>
#include <cstdint>

#define SEQ 4096
#define DIM 1024
#define NH  16
#define HD  64
#define NT  (SEQ / 64)

// Scratch. g_Vt holds V transposed [d][seq_perm] with the within-8 kv
// interleave baked in: sp(s) = (s & ~7) | ((s&1)<<2) | ((s>>1)&3).
__device__ float g_Q[SEQ * DIM];
__device__ float g_K[SEQ * DIM];
__device__ float g_Vt[DIM * SEQ];

// ---------------------------------------------------------------------------
// helpers
// ---------------------------------------------------------------------------
__device__ __forceinline__ uint32_t f2tf32(float x) {
    uint32_t r;
    asm("cvt.rna.tf32.f32 %0, %1;" : "=r"(r) : "f"(x));
    return r;
}

__device__ __forceinline__ float ex2f(float x) {
    float r;
    asm("ex2.approx.ftz.f32 %0, %1;" : "=f"(r) : "f"(x));
    return r;
}

__device__ __forceinline__ void mma_tf32(float* d, const uint32_t* a,
                                         uint32_t b0, uint32_t b1) {
    asm volatile(
        "mma.sync.aligned.m16n8k8.row.col.f32.tf32.tf32.f32 "
        "{%0,%1,%2,%3}, {%4,%5,%6,%7}, {%8,%9}, {%0,%1,%2,%3};\n"
        : "+f"(d[0]), "+f"(d[1]), "+f"(d[2]), "+f"(d[3])
        : "r"(a[0]), "r"(a[1]), "r"(a[2]), "r"(a[3]), "r"(b0), "r"(b1));
}

__device__ __forceinline__ void ldsm_x4(uint32_t& r0, uint32_t& r1,
                                        uint32_t& r2, uint32_t& r3,
                                        uint32_t addr) {
    asm volatile(
        "ldmatrix.sync.aligned.m8n8.x4.shared.b16 {%0,%1,%2,%3}, [%4];"
        : "=r"(r0), "=r"(r1), "=r"(r2), "=r"(r3) : "r"(addr));
}

__device__ __forceinline__ void cp16(uint32_t dst, const void* src) {
    asm volatile("cp.async.cg.shared.global [%0], [%1], 16;"
                 :: "r"(dst), "l"(src));
}
__device__ __forceinline__ void cp_commit() {
    asm volatile("cp.async.commit_group;");
}
template <int N> __device__ __forceinline__ void cp_wait() {
    asm volatile("cp.async.wait_group %0;" :: "n"(N));
}

// ---------------------------------------------------------------------------
// QKV projection (tf32 tensor cores). Block tile 128x128, K-step 32.
// V output (blockIdx.z==2) written transposed+permuted into g_Vt.
// ---------------------------------------------------------------------------
#define AS_STRIDE 36
#define WS_STRIDE 136

__global__ __launch_bounds__(256) void qkv_gemm_tf32(
    const float* __restrict__ A,
    const float* __restrict__ Wq, const float* __restrict__ bq,
    const float* __restrict__ Wk, const float* __restrict__ bk,
    const float* __restrict__ Wv, const float* __restrict__ bv)
{
    const float* W;
    const float* bias;
    if (blockIdx.z == 0)      { W = Wq; bias = bq; }
    else if (blockIdx.z == 1) { W = Wk; bias = bk; }
    else                      { W = Wv; bias = bv; }

    __shared__ uint32_t As[128 * AS_STRIDE];
    __shared__ uint32_t Ws[32 * WS_STRIDE];

    const int tid  = threadIdx.x;
    const int lane = tid & 31;
    const int w    = tid >> 5;
    const int g    = lane >> 2;
    const int tig  = lane & 3;
    const int wm   = (w & 3) * 32;
    const int wn   = (w >> 2) * 64;

    const int m0 = blockIdx.y * 128;
    const int n0 = blockIdx.x * 128;

    float acc[2][8][4];
#pragma unroll
    for (int mi = 0; mi < 2; mi++)
#pragma unroll
        for (int ni = 0; ni < 8; ni++)
#pragma unroll
            for (int c = 0; c < 4; c++) acc[mi][ni][c] = 0.f;

    for (int k0 = 0; k0 < DIM; k0 += 32) {
#pragma unroll
        for (int it = 0; it < 4; it++) {
            int idx = tid + it * 256;
            int row = idx >> 3;
            int c4  = (idx & 7) * 4;
            float4 v = *(const float4*)&A[(m0 + row) * DIM + k0 + c4];
            uint32_t* dst = &As[row * AS_STRIDE + c4];
            dst[0] = f2tf32(v.x); dst[1] = f2tf32(v.y);
            dst[2] = f2tf32(v.z); dst[3] = f2tf32(v.w);
        }
#pragma unroll
        for (int it = 0; it < 4; it++) {
            int idx = tid + it * 256;
            int row = idx >> 5;
            int c4  = (idx & 31) * 4;
            float4 v = *(const float4*)&W[(k0 + row) * DIM + n0 + c4];
            uint32_t* dst = &Ws[row * WS_STRIDE + c4];
            dst[0] = f2tf32(v.x); dst[1] = f2tf32(v.y);
            dst[2] = f2tf32(v.z); dst[3] = f2tf32(v.w);
        }
        __syncthreads();

#pragma unroll
        for (int kk = 0; kk < 32; kk += 8) {
            uint32_t afr[2][4];
#pragma unroll
            for (int mi = 0; mi < 2; mi++) {
                int rb = wm + mi * 16;
                afr[mi][0] = As[(rb + g) * AS_STRIDE + kk + tig];
                afr[mi][1] = As[(rb + g + 8) * AS_STRIDE + kk + tig];
                afr[mi][2] = As[(rb + g) * AS_STRIDE + kk + tig + 4];
                afr[mi][3] = As[(rb + g + 8) * AS_STRIDE + kk + tig + 4];
            }
#pragma unroll
            for (int ni = 0; ni < 8; ni++) {
                int col = wn + ni * 8 + g;
                uint32_t b0 = Ws[(kk + tig) * WS_STRIDE + col];
                uint32_t b1 = Ws[(kk + tig + 4) * WS_STRIDE + col];
#pragma unroll
                for (int mi = 0; mi < 2; mi++)
                    mma_tf32(acc[mi][ni], afr[mi], b0, b1);
            }
        }
        __syncthreads();
    }

    if (blockIdx.z != 2) {
        float* C = (blockIdx.z == 0) ? g_Q : g_K;
#pragma unroll
        for (int ni = 0; ni < 8; ni++) {
            int col = n0 + wn + ni * 8 + 2 * tig;
            float b0 = bias[col], b1 = bias[col + 1];
#pragma unroll
            for (int mi = 0; mi < 2; mi++) {
                int row = m0 + wm + mi * 16 + g;
                float2 v0 = make_float2(acc[mi][ni][0] + b0, acc[mi][ni][1] + b1);
                float2 v1 = make_float2(acc[mi][ni][2] + b0, acc[mi][ni][3] + b1);
                *(float2*)&C[row * DIM + col]       = v0;
                *(float2*)&C[(row + 8) * DIM + col] = v1;
            }
        }
    } else {
        // V: transposed + seq-permuted store into g_Vt[d][sp(seq)]
#pragma unroll
        for (int ni = 0; ni < 8; ni++) {
            int col = n0 + wn + ni * 8 + 2 * tig;
            float b0 = bias[col], b1 = bias[col + 1];
#pragma unroll
            for (int mi = 0; mi < 2; mi++) {
                int row0 = m0 + wm + mi * 16 + g;
                int row1 = row0 + 8;
                int sp0 = (row0 & ~7) | ((row0 & 1) << 2) | ((row0 >> 1) & 3);
                int sp1 = (row1 & ~7) | ((row1 & 1) << 2) | ((row1 >> 1) & 3);
                g_Vt[col * SEQ + sp0]       = acc[mi][ni][0] + b0;
                g_Vt[(col + 1) * SEQ + sp0] = acc[mi][ni][1] + b1;
                g_Vt[col * SEQ + sp1]       = acc[mi][ni][2] + b0;
                g_Vt[(col + 1) * SEQ + sp1] = acc[mi][ni][3] + b1;
            }
        }
    }
}

// ---------------------------------------------------------------------------
// Flash attention, tf32, cp.async double-buffered KV, shuffle-free PV.
// Grid (SEQ/128, NH), block 256 = 8 warps, 2 CTAs/SM.
// SMEM (dynamic): 2 stages x (K tile + Vt tile), stride 68 floats.
// ---------------------------------------------------------------------------
#define KSTRIDE 68
#define TILE_BYTES (64 * KSTRIDE * 4)
#define ATTN_SMEM (2 * 2 * TILE_BYTES)

__global__ __launch_bounds__(256, 2) void attn_tf32(float* __restrict__ out)
{
    extern __shared__ uint32_t smem_dyn[];
    const uint32_t sbase = (uint32_t)__cvta_generic_to_shared(smem_dyn);

    const int tid  = threadIdx.x;
    const int lane = tid & 31;
    const int w    = tid >> 5;
    const int g    = lane >> 2;
    const int tig  = lane & 3;
    const int h    = blockIdx.y;
    const int rowbase = blockIdx.x * 128 + w * 16;

    const int lrow = lane & 7;
    const int lmat = lane >> 3;
    // shared ldmatrix lane offset for both K and Vt phases
    const uint32_t lane_off = (uint32_t)(lrow * KSTRIDE + lmat * 4) * 4u;

    // staging indices (per thread): 4 chunks, row r, 16B unit j
    const int st_r = tid >> 4;        // base row (0..15), +16 per it
    const int st_j = tid & 15;

    // ---- stage 0 issue ----
    {
        uint32_t kb = sbase;
        uint32_t vb = sbase + TILE_BYTES;
#pragma unroll
        for (int it = 0; it < 4; it++) {
            int r = st_r + it * 16;
            uint32_t off = (uint32_t)(r * KSTRIDE + 4 * st_j) * 4u;
            cp16(kb + off, &g_K[(0 * 64 + r) * DIM + h * HD + 4 * st_j]);
            cp16(vb + off, &g_Vt[(h * HD + r) * SEQ + 0 * 64 + 4 * st_j]);
        }
        cp_commit();
    }

    // ---- Q fragments (overlap with stage-0 cp.async) ----
    const float qscale = 0.125f * 1.4426950408889634f;
    uint32_t qa[8][4];
#pragma unroll
    for (int kf = 0; kf < 8; kf++) {
        const float* qp0 = &g_Q[(rowbase + g) * DIM + h * HD + kf * 8];
        const float* qp1 = &g_Q[(rowbase + g + 8) * DIM + h * HD + kf * 8];
        qa[kf][0] = f2tf32(qp0[tig] * qscale);
        qa[kf][1] = f2tf32(qp1[tig] * qscale);
        qa[kf][2] = f2tf32(qp0[tig + 4] * qscale);
        qa[kf][3] = f2tf32(qp1[tig + 4] * qscale);
    }

    float o[8][4];
#pragma unroll
    for (int nf = 0; nf < 8; nf++)
#pragma unroll
        for (int c = 0; c < 4; c++) o[nf][c] = 0.f;
    float m0_ = -1e30f, m1_ = -1e30f;
    float l0_ = 0.f,    l1_ = 0.f;

    for (int kt = 0; kt < NT; kt++) {
        const int buf = kt & 1;
        // issue next stage
        if (kt + 1 < NT) {
            uint32_t kb = sbase + (buf ^ 1) * 2 * TILE_BYTES;
            uint32_t vb = kb + TILE_BYTES;
#pragma unroll
            for (int it = 0; it < 4; it++) {
                int r = st_r + it * 16;
                uint32_t off = (uint32_t)(r * KSTRIDE + 4 * st_j) * 4u;
                cp16(kb + off, &g_K[((kt + 1) * 64 + r) * DIM + h * HD + 4 * st_j]);
                cp16(vb + off, &g_Vt[(h * HD + r) * SEQ + (kt + 1) * 64 + 4 * st_j]);
            }
            cp_commit();
            cp_wait<1>();
        } else {
            cp_wait<0>();
        }
        __syncthreads();

        const uint32_t kbase = sbase + buf * 2 * TILE_BYTES + lane_off;
        const uint32_t vbase = kbase + TILE_BYTES;

        // ---- S = (Q*qscale) @ K^T ----
        float s[8][4];
#pragma unroll
        for (int nf = 0; nf < 8; nf++) {
            s[nf][0] = s[nf][1] = s[nf][2] = s[nf][3] = 0.f;
            uint32_t rowb = kbase + (uint32_t)(nf * 8 * KSTRIDE) * 4u;
#pragma unroll
            for (int kfp = 0; kfp < 4; kfp++) {
                uint32_t b00, b01, b10, b11;
                ldsm_x4(b00, b01, b10, b11, rowb + kfp * 64);
                mma_tf32(s[nf], qa[2 * kfp],     b00, b01);
                mma_tf32(s[nf], qa[2 * kfp + 1], b10, b11);
            }
        }

        // ---- online softmax (base 2) ----
        float mx0 = -1e30f, mx1 = -1e30f;
#pragma unroll
        for (int nf = 0; nf < 8; nf++) {
            mx0 = fmaxf(mx0, fmaxf(s[nf][0], s[nf][1]));
            mx1 = fmaxf(mx1, fmaxf(s[nf][2], s[nf][3]));
        }
        mx0 = fmaxf(mx0, __shfl_xor_sync(0xffffffffu, mx0, 1));
        mx0 = fmaxf(mx0, __shfl_xor_sync(0xffffffffu, mx0, 2));
        mx1 = fmaxf(mx1, __shfl_xor_sync(0xffffffffu, mx1, 1));
        mx1 = fmaxf(mx1, __shfl_xor_sync(0xffffffffu, mx1, 2));
        float mn0 = fmaxf(m0_, mx0);
        float mn1 = fmaxf(m1_, mx1);
        float a0 = ex2f(m0_ - mn0);
        float a1 = ex2f(m1_ - mn1);
        m0_ = mn0; m1_ = mn1;
        l0_ *= a0; l1_ *= a1;
#pragma unroll
        for (int nf = 0; nf < 8; nf++) {
            o[nf][0] *= a0; o[nf][1] *= a0;
            o[nf][2] *= a1; o[nf][3] *= a1;
        }

        // ---- probabilities in place (raw f32 bits feed tf32 mma) ----
        float rs0 = 0.f, rs1 = 0.f;
#pragma unroll
        for (int nf = 0; nf < 8; nf++) {
            float e0 = ex2f(s[nf][0] - mn0);
            float e1 = ex2f(s[nf][1] - mn0);
            float e2 = ex2f(s[nf][2] - mn1);
            float e3 = ex2f(s[nf][3] - mn1);
            rs0 += e0 + e1;
            rs1 += e2 + e3;
            // A-frag order for permuted k: {a0=colA rowg, a1=colA rowg8,
            //                              a2=colB rowg, a3=colB rowg8}
            s[nf][0] = e0; s[nf][1] = e2; s[nf][2] = e1; s[nf][3] = e3;
        }
        rs0 += __shfl_xor_sync(0xffffffffu, rs0, 1);
        rs0 += __shfl_xor_sync(0xffffffffu, rs0, 2);
        rs1 += __shfl_xor_sync(0xffffffffu, rs1, 1);
        rs1 += __shfl_xor_sync(0xffffffffu, rs1, 2);
        l0_ += rs0; l1_ += rs1;

        // ---- O += P @ V (Vt pre-transposed & pre-permuted) ----
#pragma unroll
        for (int nf = 0; nf < 8; nf++) {
            uint32_t rowb = vbase + (uint32_t)(nf * 8 * KSTRIDE) * 4u;
#pragma unroll
            for (int kfp = 0; kfp < 4; kfp++) {
                uint32_t v0, v1, v2, v3;
                ldsm_x4(v0, v1, v2, v3, rowb + kfp * 64);
                uint32_t pa0[4] = {__float_as_uint(s[2 * kfp][0]),
                                   __float_as_uint(s[2 * kfp][1]),
                                   __float_as_uint(s[2 * kfp][2]),
                                   __float_as_uint(s[2 * kfp][3])};
                uint32_t pa1[4] = {__float_as_uint(s[2 * kfp + 1][0]),
                                   __float_as_uint(s[2 * kfp + 1][1]),
                                   __float_as_uint(s[2 * kfp + 1][2]),
                                   __float_as_uint(s[2 * kfp + 1][3])};
                mma_tf32(o[nf], pa0, v0, v1);
                mma_tf32(o[nf], pa1, v2, v3);
            }
        }
        __syncthreads();
    }

    // ---- normalize + store ----
    float inv0 = 1.0f / l0_;
    float inv1 = 1.0f / l1_;
#pragma unroll
    for (int nf = 0; nf < 8; nf++) {
        int col = h * HD + nf * 8 + 2 * tig;
        float2 v0 = make_float2(o[nf][0] * inv0, o[nf][1] * inv0);
        float2 v1 = make_float2(o[nf][2] * inv1, o[nf][3] * inv1);
        *(float2*)&out[(rowbase + g) * DIM + col]     = v0;
        *(float2*)&out[(rowbase + g + 8) * DIM + col] = v1;
    }
}

extern "C" void kernel_launch(void* const* d_in, const int* in_sizes, int n_in,
                              void* d_out, int out_size)
{
    const float* hs = (const float*)d_in[0];
    const float* Wq = (const float*)d_in[1];
    const float* bq = (const float*)d_in[2];
    const float* Wk = (const float*)d_in[3];
    const float* bk = (const float*)d_in[4];
    const float* Wv = (const float*)d_in[5];
    const float* bv = (const float*)d_in[6];
    float* out = (float*)d_out;

    cudaFuncSetAttribute(attn_tf32,
                         cudaFuncAttributeMaxDynamicSharedMemorySize,
                         ATTN_SMEM);

    dim3 g_gemm(DIM / 128, SEQ / 128, 3);
    qkv_gemm_tf32<<<g_gemm, 256>>>(hs, Wq, bq, Wk, bk, Wv, bv);

    dim3 g_attn(SEQ / 128, NH);
    attn_tf32<<<g_attn, 256, ATTN_SMEM>>>(out);
}

// round 8
// speedup vs baseline: 13.3592x; 1.0034x over previous
#include <cuda_runtime.h>
#include <cuda_bf16.h>
#include <cstdint>

#define SEQ 4096
#define DIM 1024
#define NH  16
#define HD  64
#define NT  (SEQ / 64)

// Scratch. g_Vt holds V transposed [d][seq_perm], values pre-rounded to tf32,
// with the within-8 kv interleave baked in:
//   sp(s) = (s & ~7) | ((s&1)<<2) | ((s>>1)&3)
__device__ float g_Q[SEQ * DIM];
__device__ float g_K[SEQ * DIM];
__device__ float g_Vt[DIM * SEQ];

// ---------------------------------------------------------------------------
// helpers
// ---------------------------------------------------------------------------
__device__ __forceinline__ uint32_t f2tf32(float x) {
    uint32_t r;
    asm("cvt.rna.tf32.f32 %0, %1;" : "=r"(r) : "f"(x));
    return r;
}
__device__ __forceinline__ float rnd_tf32(float x) {
    return __uint_as_float(f2tf32(x));
}

__device__ __forceinline__ float ex2f(float x) {
    float r;
    asm("ex2.approx.ftz.f32 %0, %1;" : "=f"(r) : "f"(x));
    return r;
}

__device__ __forceinline__ void mma_tf32(float* d, const uint32_t* a,
                                         uint32_t b0, uint32_t b1) {
    asm volatile(
        "mma.sync.aligned.m16n8k8.row.col.f32.tf32.tf32.f32 "
        "{%0,%1,%2,%3}, {%4,%5,%6,%7}, {%8,%9}, {%0,%1,%2,%3};\n"
        : "+f"(d[0]), "+f"(d[1]), "+f"(d[2]), "+f"(d[3])
        : "r"(a[0]), "r"(a[1]), "r"(a[2]), "r"(a[3]), "r"(b0), "r"(b1));
}

__device__ __forceinline__ void ldsm_x4(uint32_t& r0, uint32_t& r1,
                                        uint32_t& r2, uint32_t& r3,
                                        uint32_t addr) {
    asm volatile(
        "ldmatrix.sync.aligned.m8n8.x4.shared.b16 {%0,%1,%2,%3}, [%4];"
        : "=r"(r0), "=r"(r1), "=r"(r2), "=r"(r3) : "r"(addr));
}

__device__ __forceinline__ void cp16(uint32_t dst, const void* src) {
    asm volatile("cp.async.cg.shared.global [%0], [%1], 16;"
                 :: "r"(dst), "l"(src));
}
__device__ __forceinline__ void cp_commit() {
    asm volatile("cp.async.commit_group;");
}
template <int N> __device__ __forceinline__ void cp_wait() {
    asm volatile("cp.async.wait_group %0;" :: "n"(N));
}

// ---------------------------------------------------------------------------
// QKV projection (tf32 tensor cores). Block tile 128x128, K-step 32.
// Outputs pre-rounded to tf32 (rna) so attention can feed raw bits to HMMA.
// V output written transposed+permuted into g_Vt via SMEM transpose.
// ---------------------------------------------------------------------------
#define AS_STRIDE 36
#define WS_STRIDE 136
#define POOL_U32 (128 * AS_STRIDE + 32 * WS_STRIDE)   // 8960

__global__ __launch_bounds__(256) void qkv_gemm_tf32(
    const float* __restrict__ A,
    const float* __restrict__ Wq, const float* __restrict__ bq,
    const float* __restrict__ Wk, const float* __restrict__ bk,
    const float* __restrict__ Wv, const float* __restrict__ bv)
{
    const float* W;
    const float* bias;
    if (blockIdx.z == 0)      { W = Wq; bias = bq; }
    else if (blockIdx.z == 1) { W = Wk; bias = bk; }
    else                      { W = Wv; bias = bv; }

    __shared__ __align__(16) uint32_t pool[POOL_U32];
    uint32_t* As = pool;                      // 128*36
    uint32_t* Ws = pool + 128 * AS_STRIDE;    // 32*136

    const int tid  = threadIdx.x;
    const int lane = tid & 31;
    const int w    = tid >> 5;
    const int g    = lane >> 2;
    const int tig  = lane & 3;
    const int wm   = (w & 3) * 32;
    const int wn   = (w >> 2) * 64;

    const int m0 = blockIdx.y * 128;
    const int n0 = blockIdx.x * 128;

    float acc[2][8][4];
#pragma unroll
    for (int mi = 0; mi < 2; mi++)
#pragma unroll
        for (int ni = 0; ni < 8; ni++)
#pragma unroll
            for (int c = 0; c < 4; c++) acc[mi][ni][c] = 0.f;

    for (int k0 = 0; k0 < DIM; k0 += 32) {
#pragma unroll
        for (int it = 0; it < 4; it++) {
            int idx = tid + it * 256;
            int row = idx >> 3;
            int c4  = (idx & 7) * 4;
            float4 v = *(const float4*)&A[(m0 + row) * DIM + k0 + c4];
            uint32_t* dst = &As[row * AS_STRIDE + c4];
            dst[0] = f2tf32(v.x); dst[1] = f2tf32(v.y);
            dst[2] = f2tf32(v.z); dst[3] = f2tf32(v.w);
        }
#pragma unroll
        for (int it = 0; it < 4; it++) {
            int idx = tid + it * 256;
            int row = idx >> 5;
            int c4  = (idx & 31) * 4;
            float4 v = *(const float4*)&W[(k0 + row) * DIM + n0 + c4];
            uint32_t* dst = &Ws[row * WS_STRIDE + c4];
            dst[0] = f2tf32(v.x); dst[1] = f2tf32(v.y);
            dst[2] = f2tf32(v.z); dst[3] = f2tf32(v.w);
        }
        __syncthreads();

#pragma unroll
        for (int kk = 0; kk < 32; kk += 8) {
            uint32_t afr[2][4];
#pragma unroll
            for (int mi = 0; mi < 2; mi++) {
                int rb = wm + mi * 16;
                afr[mi][0] = As[(rb + g) * AS_STRIDE + kk + tig];
                afr[mi][1] = As[(rb + g + 8) * AS_STRIDE + kk + tig];
                afr[mi][2] = As[(rb + g) * AS_STRIDE + kk + tig + 4];
                afr[mi][3] = As[(rb + g + 8) * AS_STRIDE + kk + tig + 4];
            }
#pragma unroll
            for (int ni = 0; ni < 8; ni++) {
                int col = wn + ni * 8 + g;
                uint32_t b0 = Ws[(kk + tig) * WS_STRIDE + col];
                uint32_t b1 = Ws[(kk + tig + 4) * WS_STRIDE + col];
#pragma unroll
                for (int mi = 0; mi < 2; mi++)
                    mma_tf32(acc[mi][ni], afr[mi], b0, b1);
            }
        }
        __syncthreads();
    }

    if (blockIdx.z != 2) {
        float* C = (blockIdx.z == 0) ? g_Q : g_K;
#pragma unroll
        for (int ni = 0; ni < 8; ni++) {
            int col = n0 + wn + ni * 8 + 2 * tig;
            float b0 = bias[col], b1 = bias[col + 1];
#pragma unroll
            for (int mi = 0; mi < 2; mi++) {
                int row = m0 + wm + mi * 16 + g;
                float2 v0 = make_float2(rnd_tf32(acc[mi][ni][0] + b0),
                                        rnd_tf32(acc[mi][ni][1] + b1));
                float2 v1 = make_float2(rnd_tf32(acc[mi][ni][2] + b0),
                                        rnd_tf32(acc[mi][ni][3] + b1));
                *(float2*)&C[row * DIM + col]       = v0;
                *(float2*)&C[(row + 8) * DIM + col] = v1;
            }
        }
    } else {
        // V: transpose in SMEM (two 64-col halves), then coalesced stores into
        // g_Vt[d][sp(seq)] with values pre-rounded to tf32.
        float* tr = (float*)pool;   // [64][132], 33 KB < pool
#pragma unroll
        for (int half = 0; half < 2; half++) {
            __syncthreads();
            if ((w >> 2) == half) {
#pragma unroll
                for (int ni = 0; ni < 8; ni++) {
                    int cl = ni * 8 + 2 * tig;              // local col in half
                    int col = n0 + half * 64 + cl;
                    float b0 = bias[col], b1 = bias[col + 1];
#pragma unroll
                    for (int mi = 0; mi < 2; mi++) {
                        int r0 = wm + mi * 16 + g;
                        int r1 = r0 + 8;
                        int sp0 = (r0 & ~7) | ((r0 & 1) << 2) | ((r0 >> 1) & 3);
                        int sp1 = (r1 & ~7) | ((r1 & 1) << 2) | ((r1 >> 1) & 3);
                        tr[cl * 132 + sp0]       = rnd_tf32(acc[mi][ni][0] + b0);
                        tr[(cl + 1) * 132 + sp0] = rnd_tf32(acc[mi][ni][1] + b1);
                        tr[cl * 132 + sp1]       = rnd_tf32(acc[mi][ni][2] + b0);
                        tr[(cl + 1) * 132 + sp1] = rnd_tf32(acc[mi][ni][3] + b1);
                    }
                }
            }
            __syncthreads();
#pragma unroll
            for (int i = tid; i < 64 * 32; i += 256) {
                int c  = i >> 5;
                int j4 = (i & 31) * 4;
                *(float4*)&g_Vt[(n0 + half * 64 + c) * SEQ + m0 + j4] =
                    *(float4*)&tr[c * 132 + j4];
            }
        }
    }
}

// ---------------------------------------------------------------------------
// Flash attention, tf32, 3-stage cp.async pipeline, one barrier per iter,
// shuffle-free PV. Grid (SEQ/128, NH), block 256 = 8 warps, 2 CTAs/SM.
// ---------------------------------------------------------------------------
#define KSTRIDE 68
#define TILE_BYTES (64 * KSTRIDE * 4)
#define STAGE_BYTES (2 * TILE_BYTES)
#define ATTN_SMEM (3 * STAGE_BYTES)

__global__ __launch_bounds__(256, 2) void attn_tf32(float* __restrict__ out)
{
    extern __shared__ uint32_t smem_dyn[];
    const uint32_t sbase = (uint32_t)__cvta_generic_to_shared(smem_dyn);

    const int tid  = threadIdx.x;
    const int lane = tid & 31;
    const int w    = tid >> 5;
    const int g    = lane >> 2;
    const int tig  = lane & 3;
    const int h    = blockIdx.y;
    const int rowbase = blockIdx.x * 128 + w * 16;

    const int lrow = lane & 7;
    const int lmat = lane >> 3;
    const uint32_t lane_off = (uint32_t)(lrow * KSTRIDE + lmat * 4) * 4u;

    const int st_r = tid >> 4;
    const int st_j = tid & 15;

    // ---- prologue: issue stages 0 and 1 as separate groups ----
#pragma unroll
    for (int st = 0; st < 2; st++) {
        uint32_t kb = sbase + st * STAGE_BYTES;
        uint32_t vb = kb + TILE_BYTES;
#pragma unroll
        for (int it = 0; it < 4; it++) {
            int r = st_r + it * 16;
            uint32_t off = (uint32_t)(r * KSTRIDE + 4 * st_j) * 4u;
            cp16(kb + off, &g_K[(st * 64 + r) * DIM + h * HD + 4 * st_j]);
            cp16(vb + off, &g_Vt[(h * HD + r) * SEQ + st * 64 + 4 * st_j]);
        }
        cp_commit();
    }

    // ---- Q fragments (overlap with prologue cp.async) ----
    const float qscale = 0.125f * 1.4426950408889634f;
    uint32_t qa[8][4];
#pragma unroll
    for (int kf = 0; kf < 8; kf++) {
        const float* qp0 = &g_Q[(rowbase + g) * DIM + h * HD + kf * 8];
        const float* qp1 = &g_Q[(rowbase + g + 8) * DIM + h * HD + kf * 8];
        qa[kf][0] = f2tf32(qp0[tig] * qscale);
        qa[kf][1] = f2tf32(qp1[tig] * qscale);
        qa[kf][2] = f2tf32(qp0[tig + 4] * qscale);
        qa[kf][3] = f2tf32(qp1[tig + 4] * qscale);
    }

    float o[8][4];
#pragma unroll
    for (int nf = 0; nf < 8; nf++)
#pragma unroll
        for (int c = 0; c < 4; c++) o[nf][c] = 0.f;
    float m0_ = -1e30f, m1_ = -1e30f;
    float l0_ = 0.f,    l1_ = 0.f;

    int buf = 0;           // stage buffer index (kt % 3)
    for (int kt = 0; kt < NT; kt++) {
        // wait for stage kt (one newer group may stay in flight)
        if (kt + 1 < NT) cp_wait<1>(); else cp_wait<0>();
        __syncthreads();   // data visible to all; all warps done with kt-1

        // issue stage kt+2 into buffer (kt+2)%3 = (buf+2)%3
        if (kt + 2 < NT) {
            int nb = buf + 2; if (nb >= 3) nb -= 3;
            uint32_t kb = sbase + nb * STAGE_BYTES;
            uint32_t vb = kb + TILE_BYTES;
#pragma unroll
            for (int it = 0; it < 4; it++) {
                int r = st_r + it * 16;
                uint32_t off = (uint32_t)(r * KSTRIDE + 4 * st_j) * 4u;
                cp16(kb + off, &g_K[((kt + 2) * 64 + r) * DIM + h * HD + 4 * st_j]);
                cp16(vb + off, &g_Vt[(h * HD + r) * SEQ + (kt + 2) * 64 + 4 * st_j]);
            }
            cp_commit();
        }

        const uint32_t kbase = sbase + buf * STAGE_BYTES + lane_off;
        const uint32_t vbase = kbase + TILE_BYTES;

        // ---- S = (Q*qscale) @ K^T ----
        float s[8][4];
#pragma unroll
        for (int nf = 0; nf < 8; nf++) {
            s[nf][0] = s[nf][1] = s[nf][2] = s[nf][3] = 0.f;
            uint32_t rowb = kbase + (uint32_t)(nf * 8 * KSTRIDE) * 4u;
#pragma unroll
            for (int kfp = 0; kfp < 4; kfp++) {
                uint32_t b00, b01, b10, b11;
                ldsm_x4(b00, b01, b10, b11, rowb + kfp * 64);
                mma_tf32(s[nf], qa[2 * kfp],     b00, b01);
                mma_tf32(s[nf], qa[2 * kfp + 1], b10, b11);
            }
        }

        // ---- online softmax (base 2) ----
        float mx0 = -1e30f, mx1 = -1e30f;
#pragma unroll
        for (int nf = 0; nf < 8; nf++) {
            mx0 = fmaxf(mx0, fmaxf(s[nf][0], s[nf][1]));
            mx1 = fmaxf(mx1, fmaxf(s[nf][2], s[nf][3]));
        }
        mx0 = fmaxf(mx0, __shfl_xor_sync(0xffffffffu, mx0, 1));
        mx0 = fmaxf(mx0, __shfl_xor_sync(0xffffffffu, mx0, 2));
        mx1 = fmaxf(mx1, __shfl_xor_sync(0xffffffffu, mx1, 1));
        mx1 = fmaxf(mx1, __shfl_xor_sync(0xffffffffu, mx1, 2));
        float mn0 = fmaxf(m0_, mx0);
        float mn1 = fmaxf(m1_, mx1);
        float a0 = ex2f(m0_ - mn0);
        float a1 = ex2f(m1_ - mn1);
        m0_ = mn0; m1_ = mn1;
        l0_ *= a0; l1_ *= a1;
#pragma unroll
        for (int nf = 0; nf < 8; nf++) {
            o[nf][0] *= a0; o[nf][1] *= a0;
            o[nf][2] *= a1; o[nf][3] *= a1;
        }

        // ---- probabilities -> rounded tf32 A-fragments (permuted k order) ----
        float rs0 = 0.f, rs1 = 0.f;
        uint32_t p[8][4];
#pragma unroll
        for (int nf = 0; nf < 8; nf++) {
            float e0 = ex2f(s[nf][0] - mn0);
            float e1 = ex2f(s[nf][1] - mn0);
            float e2 = ex2f(s[nf][2] - mn1);
            float e3 = ex2f(s[nf][3] - mn1);
            rs0 += e0 + e1;
            rs1 += e2 + e3;
            p[nf][0] = f2tf32(e0);
            p[nf][1] = f2tf32(e2);
            p[nf][2] = f2tf32(e1);
            p[nf][3] = f2tf32(e3);
        }
        rs0 += __shfl_xor_sync(0xffffffffu, rs0, 1);
        rs0 += __shfl_xor_sync(0xffffffffu, rs0, 2);
        rs1 += __shfl_xor_sync(0xffffffffu, rs1, 1);
        rs1 += __shfl_xor_sync(0xffffffffu, rs1, 2);
        l0_ += rs0; l1_ += rs1;

        // ---- O += P @ V (Vt pre-transposed, pre-permuted, pre-rounded) ----
#pragma unroll
        for (int nf = 0; nf < 8; nf++) {
            uint32_t rowb = vbase + (uint32_t)(nf * 8 * KSTRIDE) * 4u;
#pragma unroll
            for (int kfp = 0; kfp < 4; kfp++) {
                uint32_t v0, v1, v2, v3;
                ldsm_x4(v0, v1, v2, v3, rowb + kfp * 64);
                mma_tf32(o[nf], p[2 * kfp],     v0, v1);
                mma_tf32(o[nf], p[2 * kfp + 1], v2, v3);
            }
        }

        buf++; if (buf >= 3) buf = 0;
    }

    // ---- normalize + store ----
    float inv0 = 1.0f / l0_;
    float inv1 = 1.0f / l1_;
#pragma unroll
    for (int nf = 0; nf < 8; nf++) {
        int col = h * HD + nf * 8 + 2 * tig;
        float2 v0 = make_float2(o[nf][0] * inv0, o[nf][1] * inv0);
        float2 v1 = make_float2(o[nf][2] * inv1, o[nf][3] * inv1);
        *(float2*)&out[(rowbase + g) * DIM + col]     = v0;
        *(float2*)&out[(rowbase + g + 8) * DIM + col] = v1;
    }
}

extern "C" void kernel_launch(void* const* d_in, const int* in_sizes, int n_in,
                              void* d_out, int out_size)
{
    const float* hs = (const float*)d_in[0];
    const float* Wq = (const float*)d_in[1];
    const float* bq = (const float*)d_in[2];
    const float* Wk = (const float*)d_in[3];
    const float* bk = (const float*)d_in[4];
    const float* Wv = (const float*)d_in[5];
    const float* bv = (const float*)d_in[6];
    float* out = (float*)d_out;

    cudaFuncSetAttribute(attn_tf32,
                         cudaFuncAttributeMaxDynamicSharedMemorySize,
                         ATTN_SMEM);

    dim3 g_gemm(DIM / 128, SEQ / 128, 3);
    qkv_gemm_tf32<<<g_gemm, 256>>>(hs, Wq, bq, Wk, bk, Wv, bv);

    dim3 g_attn(SEQ / 128, NH);
    attn_tf32<<<g_attn, 256, ATTN_SMEM>>>(out);
}

// round 9
// speedup vs baseline: 14.3917x; 1.0773x over previous
#include <cuda_runtime.h>
#include <cuda_bf16.h>
#include <cstdint>

#define SEQ 4096
#define DIM 1024
#define NH  16
#define HD  64
#define NT  (SEQ / 64)

// Scratch. g_Vt holds V transposed [d][seq_perm], values pre-rounded to tf32,
// with the within-8 kv interleave baked in:
//   sp(s) = (s & ~7) | ((s&1)<<2) | ((s>>1)&3)
__device__ float g_Q[SEQ * DIM];
__device__ float g_K[SEQ * DIM];
__device__ float g_Vt[DIM * SEQ];

// ---------------------------------------------------------------------------
// helpers
// ---------------------------------------------------------------------------
__device__ __forceinline__ uint32_t f2tf32(float x) {
    uint32_t r;
    asm("cvt.rna.tf32.f32 %0, %1;" : "=r"(r) : "f"(x));
    return r;
}
__device__ __forceinline__ float rnd_tf32(float x) {
    return __uint_as_float(f2tf32(x));
}

__device__ __forceinline__ float ex2f(float x) {
    float r;
    asm("ex2.approx.ftz.f32 %0, %1;" : "=f"(r) : "f"(x));
    return r;
}

__device__ __forceinline__ void mma_tf32(float* d, const uint32_t* a,
                                         uint32_t b0, uint32_t b1) {
    asm volatile(
        "mma.sync.aligned.m16n8k8.row.col.f32.tf32.tf32.f32 "
        "{%0,%1,%2,%3}, {%4,%5,%6,%7}, {%8,%9}, {%0,%1,%2,%3};\n"
        : "+f"(d[0]), "+f"(d[1]), "+f"(d[2]), "+f"(d[3])
        : "r"(a[0]), "r"(a[1]), "r"(a[2]), "r"(a[3]), "r"(b0), "r"(b1));
}

// P operands live in float regs (tf32-rounded bit patterns)
__device__ __forceinline__ void mma_tf32f(float* d, const float* a,
                                          uint32_t b0, uint32_t b1) {
    uint32_t pa[4] = {__float_as_uint(a[0]), __float_as_uint(a[1]),
                      __float_as_uint(a[2]), __float_as_uint(a[3])};
    mma_tf32(d, pa, b0, b1);
}

__device__ __forceinline__ void ldsm_x4(uint32_t& r0, uint32_t& r1,
                                        uint32_t& r2, uint32_t& r3,
                                        uint32_t addr) {
    asm volatile(
        "ldmatrix.sync.aligned.m8n8.x4.shared.b16 {%0,%1,%2,%3}, [%4];"
        : "=r"(r0), "=r"(r1), "=r"(r2), "=r"(r3) : "r"(addr));
}

__device__ __forceinline__ void cp16(uint32_t dst, const void* src) {
    asm volatile("cp.async.cg.shared.global [%0], [%1], 16;"
                 :: "r"(dst), "l"(src));
}
__device__ __forceinline__ void cp_commit() {
    asm volatile("cp.async.commit_group;");
}
template <int N> __device__ __forceinline__ void cp_wait() {
    asm volatile("cp.async.wait_group %0;" :: "n"(N));
}

// ---------------------------------------------------------------------------
// QKV projection (tf32 tensor cores). Block tile 128x128, K-step 32.
// Outputs pre-rounded to tf32 (rna) so attention can feed raw bits to HMMA.
// V output written transposed+permuted into g_Vt via SMEM transpose.
// ---------------------------------------------------------------------------
#define AS_STRIDE 36
#define WS_STRIDE 136
#define POOL_U32 (128 * AS_STRIDE + 32 * WS_STRIDE)   // 8960

__global__ __launch_bounds__(256) void qkv_gemm_tf32(
    const float* __restrict__ A,
    const float* __restrict__ Wq, const float* __restrict__ bq,
    const float* __restrict__ Wk, const float* __restrict__ bk,
    const float* __restrict__ Wv, const float* __restrict__ bv)
{
    const float* W;
    const float* bias;
    if (blockIdx.z == 0)      { W = Wq; bias = bq; }
    else if (blockIdx.z == 1) { W = Wk; bias = bk; }
    else                      { W = Wv; bias = bv; }

    __shared__ __align__(16) uint32_t pool[POOL_U32];
    uint32_t* As = pool;                      // 128*36
    uint32_t* Ws = pool + 128 * AS_STRIDE;    // 32*136

    const int tid  = threadIdx.x;
    const int lane = tid & 31;
    const int w    = tid >> 5;
    const int g    = lane >> 2;
    const int tig  = lane & 3;
    const int wm   = (w & 3) * 32;
    const int wn   = (w >> 2) * 64;

    const int m0 = blockIdx.y * 128;
    const int n0 = blockIdx.x * 128;

    float acc[2][8][4];
#pragma unroll
    for (int mi = 0; mi < 2; mi++)
#pragma unroll
        for (int ni = 0; ni < 8; ni++)
#pragma unroll
            for (int c = 0; c < 4; c++) acc[mi][ni][c] = 0.f;

    for (int k0 = 0; k0 < DIM; k0 += 32) {
#pragma unroll
        for (int it = 0; it < 4; it++) {
            int idx = tid + it * 256;
            int row = idx >> 3;
            int c4  = (idx & 7) * 4;
            float4 v = *(const float4*)&A[(m0 + row) * DIM + k0 + c4];
            uint32_t* dst = &As[row * AS_STRIDE + c4];
            dst[0] = f2tf32(v.x); dst[1] = f2tf32(v.y);
            dst[2] = f2tf32(v.z); dst[3] = f2tf32(v.w);
        }
#pragma unroll
        for (int it = 0; it < 4; it++) {
            int idx = tid + it * 256;
            int row = idx >> 5;
            int c4  = (idx & 31) * 4;
            float4 v = *(const float4*)&W[(k0 + row) * DIM + n0 + c4];
            uint32_t* dst = &Ws[row * WS_STRIDE + c4];
            dst[0] = f2tf32(v.x); dst[1] = f2tf32(v.y);
            dst[2] = f2tf32(v.z); dst[3] = f2tf32(v.w);
        }
        __syncthreads();

#pragma unroll
        for (int kk = 0; kk < 32; kk += 8) {
            uint32_t afr[2][4];
#pragma unroll
            for (int mi = 0; mi < 2; mi++) {
                int rb = wm + mi * 16;
                afr[mi][0] = As[(rb + g) * AS_STRIDE + kk + tig];
                afr[mi][1] = As[(rb + g + 8) * AS_STRIDE + kk + tig];
                afr[mi][2] = As[(rb + g) * AS_STRIDE + kk + tig + 4];
                afr[mi][3] = As[(rb + g + 8) * AS_STRIDE + kk + tig + 4];
            }
#pragma unroll
            for (int ni = 0; ni < 8; ni++) {
                int col = wn + ni * 8 + g;
                uint32_t b0 = Ws[(kk + tig) * WS_STRIDE + col];
                uint32_t b1 = Ws[(kk + tig + 4) * WS_STRIDE + col];
#pragma unroll
                for (int mi = 0; mi < 2; mi++)
                    mma_tf32(acc[mi][ni], afr[mi], b0, b1);
            }
        }
        __syncthreads();
    }

    if (blockIdx.z != 2) {
        float* C = (blockIdx.z == 0) ? g_Q : g_K;
#pragma unroll
        for (int ni = 0; ni < 8; ni++) {
            int col = n0 + wn + ni * 8 + 2 * tig;
            float b0 = bias[col], b1 = bias[col + 1];
#pragma unroll
            for (int mi = 0; mi < 2; mi++) {
                int row = m0 + wm + mi * 16 + g;
                float2 v0 = make_float2(rnd_tf32(acc[mi][ni][0] + b0),
                                        rnd_tf32(acc[mi][ni][1] + b1));
                float2 v1 = make_float2(rnd_tf32(acc[mi][ni][2] + b0),
                                        rnd_tf32(acc[mi][ni][3] + b1));
                *(float2*)&C[row * DIM + col]       = v0;
                *(float2*)&C[(row + 8) * DIM + col] = v1;
            }
        }
    } else {
        // V: transpose in SMEM (two 64-col halves), then coalesced stores into
        // g_Vt[d][sp(seq)] with values pre-rounded to tf32.
        float* tr = (float*)pool;   // [64][132], 33 KB < pool
#pragma unroll
        for (int half = 0; half < 2; half++) {
            __syncthreads();
            if ((w >> 2) == half) {
#pragma unroll
                for (int ni = 0; ni < 8; ni++) {
                    int cl = ni * 8 + 2 * tig;              // local col in half
                    int col = n0 + half * 64 + cl;
                    float b0 = bias[col], b1 = bias[col + 1];
#pragma unroll
                    for (int mi = 0; mi < 2; mi++) {
                        int r0 = wm + mi * 16 + g;
                        int r1 = r0 + 8;
                        int sp0 = (r0 & ~7) | ((r0 & 1) << 2) | ((r0 >> 1) & 3);
                        int sp1 = (r1 & ~7) | ((r1 & 1) << 2) | ((r1 >> 1) & 3);
                        tr[cl * 132 + sp0]       = rnd_tf32(acc[mi][ni][0] + b0);
                        tr[(cl + 1) * 132 + sp0] = rnd_tf32(acc[mi][ni][1] + b1);
                        tr[cl * 132 + sp1]       = rnd_tf32(acc[mi][ni][2] + b0);
                        tr[(cl + 1) * 132 + sp1] = rnd_tf32(acc[mi][ni][3] + b1);
                    }
                }
            }
            __syncthreads();
#pragma unroll
            for (int i = tid; i < 64 * 32; i += 256) {
                int c  = i >> 5;
                int j4 = (i & 31) * 4;
                *(float4*)&g_Vt[(n0 + half * 64 + c) * SEQ + m0 + j4] =
                    *(float4*)&tr[c * 132 + j4];
            }
        }
    }
}

// ---------------------------------------------------------------------------
// Flash attention, tf32, m32 warp tile (each K/V fragment feeds 2 mmas),
// 3-stage cp.async pipeline, shuffle-free PV.
// Grid (SEQ/128, NH), block 128 = 4 warps; warp w owns Q rows w*32..+31.
// 2 CTAs/SM (regs ~220, smem 104KB/CTA).
// ---------------------------------------------------------------------------
#define KSTRIDE 68
#define TILE_BYTES (64 * KSTRIDE * 4)
#define STAGE_BYTES (2 * TILE_BYTES)
#define ATTN_SMEM (3 * STAGE_BYTES)

__global__ __launch_bounds__(128, 2) void attn_tf32(float* __restrict__ out)
{
    extern __shared__ uint32_t smem_dyn[];
    const uint32_t sbase = (uint32_t)__cvta_generic_to_shared(smem_dyn);

    const int tid  = threadIdx.x;
    const int lane = tid & 31;
    const int w    = tid >> 5;        // 0..3
    const int g    = lane >> 2;
    const int tig  = lane & 3;
    const int h    = blockIdx.y;
    const int rowbase = blockIdx.x * 128 + w * 32;

    const int lrow = lane & 7;
    const int lmat = lane >> 3;
    const uint32_t lane_off = (uint32_t)(lrow * KSTRIDE + lmat * 4) * 4u;

    const int st_r = tid >> 4;        // 0..7
    const int st_j = tid & 15;

    // ---- prologue: issue stages 0 and 1 ----
#pragma unroll
    for (int st = 0; st < 2; st++) {
        uint32_t kb = sbase + st * STAGE_BYTES;
        uint32_t vb = kb + TILE_BYTES;
#pragma unroll
        for (int it = 0; it < 8; it++) {
            int r = st_r + it * 8;
            uint32_t off = (uint32_t)(r * KSTRIDE + 4 * st_j) * 4u;
            cp16(kb + off, &g_K[(st * 64 + r) * DIM + h * HD + 4 * st_j]);
            cp16(vb + off, &g_Vt[(h * HD + r) * SEQ + st * 64 + 4 * st_j]);
        }
        cp_commit();
    }

    // ---- Q fragments for both m16 tiles (rows +0..15, +16..31) ----
    const float qscale = 0.125f * 1.4426950408889634f;
    uint32_t qa[2][8][4];
#pragma unroll
    for (int t = 0; t < 2; t++) {
#pragma unroll
        for (int kf = 0; kf < 8; kf++) {
            const float* qp0 = &g_Q[(rowbase + t * 16 + g) * DIM + h * HD + kf * 8];
            const float* qp1 = &g_Q[(rowbase + t * 16 + g + 8) * DIM + h * HD + kf * 8];
            qa[t][kf][0] = f2tf32(qp0[tig] * qscale);
            qa[t][kf][1] = f2tf32(qp1[tig] * qscale);
            qa[t][kf][2] = f2tf32(qp0[tig + 4] * qscale);
            qa[t][kf][3] = f2tf32(qp1[tig + 4] * qscale);
        }
    }

    float o[2][8][4];
#pragma unroll
    for (int t = 0; t < 2; t++)
#pragma unroll
        for (int nf = 0; nf < 8; nf++)
#pragma unroll
            for (int c = 0; c < 4; c++) o[t][nf][c] = 0.f;
    float m_[4] = {-1e30f, -1e30f, -1e30f, -1e30f};  // [t*2 + half]
    float l_[4] = {0.f, 0.f, 0.f, 0.f};

    int buf = 0;
    for (int kt = 0; kt < NT; kt++) {
        if (kt + 1 < NT) cp_wait<1>(); else cp_wait<0>();
        __syncthreads();

        if (kt + 2 < NT) {
            int nb = buf + 2; if (nb >= 3) nb -= 3;
            uint32_t kb = sbase + nb * STAGE_BYTES;
            uint32_t vb = kb + TILE_BYTES;
#pragma unroll
            for (int it = 0; it < 8; it++) {
                int r = st_r + it * 8;
                uint32_t off = (uint32_t)(r * KSTRIDE + 4 * st_j) * 4u;
                cp16(kb + off, &g_K[((kt + 2) * 64 + r) * DIM + h * HD + 4 * st_j]);
                cp16(vb + off, &g_Vt[(h * HD + r) * SEQ + (kt + 2) * 64 + 4 * st_j]);
            }
            cp_commit();
        }

        const uint32_t kbase = sbase + buf * STAGE_BYTES + lane_off;
        const uint32_t vbase = kbase + TILE_BYTES;

        // ---- S = (Q*qscale) @ K^T : each K fragment feeds both m16 tiles ----
        float s[2][8][4];
#pragma unroll
        for (int nf = 0; nf < 8; nf++) {
            s[0][nf][0] = s[0][nf][1] = s[0][nf][2] = s[0][nf][3] = 0.f;
            s[1][nf][0] = s[1][nf][1] = s[1][nf][2] = s[1][nf][3] = 0.f;
            uint32_t rowb = kbase + (uint32_t)(nf * 8 * KSTRIDE) * 4u;
#pragma unroll
            for (int kfp = 0; kfp < 4; kfp++) {
                uint32_t b00, b01, b10, b11;
                ldsm_x4(b00, b01, b10, b11, rowb + kfp * 64);
                mma_tf32(s[0][nf], qa[0][2 * kfp],     b00, b01);
                mma_tf32(s[0][nf], qa[0][2 * kfp + 1], b10, b11);
                mma_tf32(s[1][nf], qa[1][2 * kfp],     b00, b01);
                mma_tf32(s[1][nf], qa[1][2 * kfp + 1], b10, b11);
            }
        }

        // ---- online softmax (base 2), per m16 tile ----
#pragma unroll
        for (int t = 0; t < 2; t++) {
            float mx0 = -1e30f, mx1 = -1e30f;
#pragma unroll
            for (int nf = 0; nf < 8; nf++) {
                mx0 = fmaxf(mx0, fmaxf(s[t][nf][0], s[t][nf][1]));
                mx1 = fmaxf(mx1, fmaxf(s[t][nf][2], s[t][nf][3]));
            }
            mx0 = fmaxf(mx0, __shfl_xor_sync(0xffffffffu, mx0, 1));
            mx0 = fmaxf(mx0, __shfl_xor_sync(0xffffffffu, mx0, 2));
            mx1 = fmaxf(mx1, __shfl_xor_sync(0xffffffffu, mx1, 1));
            mx1 = fmaxf(mx1, __shfl_xor_sync(0xffffffffu, mx1, 2));
            float mn0 = fmaxf(m_[2 * t],     mx0);
            float mn1 = fmaxf(m_[2 * t + 1], mx1);
            float a0 = ex2f(m_[2 * t]     - mn0);
            float a1 = ex2f(m_[2 * t + 1] - mn1);
            m_[2 * t] = mn0; m_[2 * t + 1] = mn1;
            l_[2 * t] *= a0; l_[2 * t + 1] *= a1;
#pragma unroll
            for (int nf = 0; nf < 8; nf++) {
                o[t][nf][0] *= a0; o[t][nf][1] *= a0;
                o[t][nf][2] *= a1; o[t][nf][3] *= a1;
            }

            // probabilities -> tf32-rounded A-fragments in place (permuted k)
            float rs0 = 0.f, rs1 = 0.f;
#pragma unroll
            for (int nf = 0; nf < 8; nf++) {
                float e0 = ex2f(s[t][nf][0] - mn0);
                float e1 = ex2f(s[t][nf][1] - mn0);
                float e2 = ex2f(s[t][nf][2] - mn1);
                float e3 = ex2f(s[t][nf][3] - mn1);
                rs0 += e0 + e1;
                rs1 += e2 + e3;
                s[t][nf][0] = rnd_tf32(e0);
                s[t][nf][1] = rnd_tf32(e2);
                s[t][nf][2] = rnd_tf32(e1);
                s[t][nf][3] = rnd_tf32(e3);
            }
            rs0 += __shfl_xor_sync(0xffffffffu, rs0, 1);
            rs0 += __shfl_xor_sync(0xffffffffu, rs0, 2);
            rs1 += __shfl_xor_sync(0xffffffffu, rs1, 1);
            rs1 += __shfl_xor_sync(0xffffffffu, rs1, 2);
            l_[2 * t] += rs0; l_[2 * t + 1] += rs1;
        }

        // ---- O += P @ V : each V fragment feeds both m16 tiles ----
#pragma unroll
        for (int nf = 0; nf < 8; nf++) {
            uint32_t rowb = vbase + (uint32_t)(nf * 8 * KSTRIDE) * 4u;
#pragma unroll
            for (int kfp = 0; kfp < 4; kfp++) {
                uint32_t v0, v1, v2, v3;
                ldsm_x4(v0, v1, v2, v3, rowb + kfp * 64);
                mma_tf32f(o[0][nf], s[0][2 * kfp],     v0, v1);
                mma_tf32f(o[0][nf], s[0][2 * kfp + 1], v2, v3);
                mma_tf32f(o[1][nf], s[1][2 * kfp],     v0, v1);
                mma_tf32f(o[1][nf], s[1][2 * kfp + 1], v2, v3);
            }
        }

        buf++; if (buf >= 3) buf = 0;
    }

    // ---- normalize + store ----
#pragma unroll
    for (int t = 0; t < 2; t++) {
        float inv0 = 1.0f / l_[2 * t];
        float inv1 = 1.0f / l_[2 * t + 1];
#pragma unroll
        for (int nf = 0; nf < 8; nf++) {
            int col = h * HD + nf * 8 + 2 * tig;
            float2 v0 = make_float2(o[t][nf][0] * inv0, o[t][nf][1] * inv0);
            float2 v1 = make_float2(o[t][nf][2] * inv1, o[t][nf][3] * inv1);
            *(float2*)&out[(rowbase + t * 16 + g) * DIM + col]     = v0;
            *(float2*)&out[(rowbase + t * 16 + g + 8) * DIM + col] = v1;
        }
    }
}

extern "C" void kernel_launch(void* const* d_in, const int* in_sizes, int n_in,
                              void* d_out, int out_size)
{
    const float* hs = (const float*)d_in[0];
    const float* Wq = (const float*)d_in[1];
    const float* bq = (const float*)d_in[2];
    const float* Wk = (const float*)d_in[3];
    const float* bk = (const float*)d_in[4];
    const float* Wv = (const float*)d_in[5];
    const float* bv = (const float*)d_in[6];
    float* out = (float*)d_out;

    cudaFuncSetAttribute(attn_tf32,
                         cudaFuncAttributeMaxDynamicSharedMemorySize,
                         ATTN_SMEM);

    dim3 g_gemm(DIM / 128, SEQ / 128, 3);
    qkv_gemm_tf32<<<g_gemm, 256>>>(hs, Wq, bq, Wk, bk, Wv, bv);

    dim3 g_attn(SEQ / 128, NH);
    attn_tf32<<<g_attn, 128, ATTN_SMEM>>>(out);
}

// round 10
// speedup vs baseline: 25.8009x; 1.7928x over previous
#include <cuda_runtime.h>
#include <cuda_fp16.h>
#include <cstdint>

#define SEQ 4096
#define DIM 1024
#define NH  16
#define HD  64
#define NT  (SEQ / 64)

// fp16 scratch. __device__ globals = sanctioned scratch.
__device__ __half g_Ah[SEQ * DIM];        // hidden_states, fp16
__device__ __half g_Wh[3][DIM * DIM];     // Wq, Wk, Wv, fp16
__device__ __half g_Qh[SEQ * DIM];        // Q * 0.125*log2e, fp16
__device__ __half g_Kh[SEQ * DIM];        // K, fp16
__device__ __half g_Vh[SEQ * DIM];        // V, fp16 (natural [s][d] layout)

// ---------------------------------------------------------------------------
// helpers
// ---------------------------------------------------------------------------
__device__ __forceinline__ uint32_t packh2(float hi, float lo) {
    uint32_t r;
    asm("cvt.rn.f16x2.f32 %0, %1, %2;" : "=r"(r) : "f"(hi), "f"(lo));
    return r;
}

__device__ __forceinline__ float ex2f(float x) {
    float r;
    asm("ex2.approx.ftz.f32 %0, %1;" : "=f"(r) : "f"(x));
    return r;
}

__device__ __forceinline__ void mma_f16(float* d, const uint32_t* a,
                                        uint32_t b0, uint32_t b1) {
    asm volatile(
        "mma.sync.aligned.m16n8k16.row.col.f32.f16.f16.f32 "
        "{%0,%1,%2,%3}, {%4,%5,%6,%7}, {%8,%9}, {%0,%1,%2,%3};\n"
        : "+f"(d[0]), "+f"(d[1]), "+f"(d[2]), "+f"(d[3])
        : "r"(a[0]), "r"(a[1]), "r"(a[2]), "r"(a[3]), "r"(b0), "r"(b1));
}

__device__ __forceinline__ void ldsm_x4(uint32_t& r0, uint32_t& r1,
                                        uint32_t& r2, uint32_t& r3,
                                        uint32_t addr) {
    asm volatile(
        "ldmatrix.sync.aligned.m8n8.x4.shared.b16 {%0,%1,%2,%3}, [%4];"
        : "=r"(r0), "=r"(r1), "=r"(r2), "=r"(r3) : "r"(addr));
}

__device__ __forceinline__ void ldsm_x4_t(uint32_t& r0, uint32_t& r1,
                                          uint32_t& r2, uint32_t& r3,
                                          uint32_t addr) {
    asm volatile(
        "ldmatrix.sync.aligned.m8n8.x4.trans.shared.b16 {%0,%1,%2,%3}, [%4];"
        : "=r"(r0), "=r"(r1), "=r"(r2), "=r"(r3) : "r"(addr));
}

__device__ __forceinline__ void cp16(uint32_t dst, const void* src) {
    asm volatile("cp.async.cg.shared.global [%0], [%1], 16;"
                 :: "r"(dst), "l"(src));
}
__device__ __forceinline__ void cp_commit() {
    asm volatile("cp.async.commit_group;");
}
template <int N> __device__ __forceinline__ void cp_wait() {
    asm volatile("cp.async.wait_group %0;" :: "n"(N));
}

// ---------------------------------------------------------------------------
// fp32 -> fp16 pre-convert (hidden_states + 3 weight matrices)
// grid (4096, 1, 4); z=0 -> A, z=1..3 -> W
// ---------------------------------------------------------------------------
__global__ void cvt_fp16(const float* __restrict__ hs,
                         const float* __restrict__ Wq,
                         const float* __restrict__ Wk,
                         const float* __restrict__ Wv)
{
    const int z = blockIdx.z;
    const float* src;
    __half* dst;
    int n4;
    if (z == 0)      { src = hs; dst = g_Ah;    n4 = SEQ * DIM / 4; }
    else if (z == 1) { src = Wq; dst = g_Wh[0]; n4 = DIM * DIM / 4; }
    else if (z == 2) { src = Wk; dst = g_Wh[1]; n4 = DIM * DIM / 4; }
    else             { src = Wv; dst = g_Wh[2]; n4 = DIM * DIM / 4; }
    int i = blockIdx.x * blockDim.x + threadIdx.x;
    if (i < n4) {
        float4 v = *(const float4*)&src[i * 4];
        uint2 u = make_uint2(packh2(v.y, v.x), packh2(v.w, v.z));
        *(uint2*)&dst[i * 4] = u;
    }
}

// ---------------------------------------------------------------------------
// QKV projection, fp16 tensor cores (m16n8k16), cp.async double-buffered.
// Block tile 128x128, K-step 32, 8 warps, warp tile 32x64.
// z selects Q (scaled by 0.125*log2e) / K / V. All outputs fp16.
// ---------------------------------------------------------------------------
#define GA_ROW_B 80                       // A tile row stride bytes (32h + pad)
#define GW_ROW_B 272                      // W tile row stride bytes (128h + pad)
#define GA_BYTES (128 * GA_ROW_B)         // 10240
#define GW_BYTES (32 * GW_ROW_B)          // 8704
#define GSTG (GA_BYTES + GW_BYTES)        // 18944

__global__ __launch_bounds__(256, 2) void qkv_gemm_f16(
    const float* __restrict__ bq,
    const float* __restrict__ bk,
    const float* __restrict__ bv)
{
    __shared__ __align__(16) uint8_t gsm[2 * GSTG];
    const uint32_t gbase = (uint32_t)__cvta_generic_to_shared(gsm);

    const int zi = blockIdx.z;
    const float* bias = (zi == 0) ? bq : (zi == 1) ? bk : bv;
    const __half* Wz = g_Wh[zi];

    const int tid  = threadIdx.x;
    const int lane = tid & 31;
    const int w    = tid >> 5;
    const int g    = lane >> 2;
    const int tig  = lane & 3;
    const int lrow = lane & 7;
    const int lmat = lane >> 3;
    const int wm   = (w & 3) * 32;
    const int wn   = (w >> 2) * 64;

    const int m0 = blockIdx.y * 128;
    const int n0 = blockIdx.x * 128;

    // per-lane ldmatrix offsets within a stage
    const uint32_t a_lane = (uint32_t)(((lmat & 1) * 8 + lrow) * GA_ROW_B +
                                       ((lmat >> 1) * 8) * 2);
    const uint32_t w_lane = (uint32_t)(((lmat & 1) * 8 + lrow) * GW_ROW_B +
                                       ((lmat >> 1) * 8) * 2);

    float acc[2][8][4];
#pragma unroll
    for (int mi = 0; mi < 2; mi++)
#pragma unroll
        for (int ni = 0; ni < 8; ni++)
#pragma unroll
            for (int c = 0; c < 4; c++) acc[mi][ni][c] = 0.f;

    // stage issue helper (inlined twice)
#define G_ISSUE(BUF, K0)                                                      \
    {                                                                         \
        uint32_t ab = gbase + (BUF) * GSTG;                                   \
        uint32_t wb = ab + GA_BYTES;                                          \
        _Pragma("unroll")                                                     \
        for (int it = 0; it < 2; it++) {                                      \
            int id = tid + it * 256;                                          \
            int r = id >> 2, j = id & 3;                                      \
            cp16(ab + r * GA_ROW_B + j * 16,                                  \
                 &g_Ah[(m0 + r) * DIM + (K0) + j * 8]);                       \
        }                                                                     \
        _Pragma("unroll")                                                     \
        for (int it = 0; it < 2; it++) {                                      \
            int id = tid + it * 256;                                          \
            int r = id >> 4, j = id & 15;                                     \
            cp16(wb + r * GW_ROW_B + j * 16,                                  \
                 &Wz[((K0) + r) * DIM + n0 + j * 8]);                         \
        }                                                                     \
        cp_commit();                                                          \
    }

    G_ISSUE(0, 0);

    for (int ki = 0; ki < DIM / 32; ki++) {
        if (ki + 1 < DIM / 32) {
            G_ISSUE((ki + 1) & 1, (ki + 1) * 32);
            cp_wait<1>();
        } else {
            cp_wait<0>();
        }
        __syncthreads();

        const int buf = ki & 1;
        const uint32_t ab = gbase + buf * GSTG;
        const uint32_t wb = ab + GA_BYTES;

#pragma unroll
        for (int kk = 0; kk < 2; kk++) {
            uint32_t af[2][4];
#pragma unroll
            for (int mi = 0; mi < 2; mi++) {
                uint32_t addr = ab + (uint32_t)((wm + mi * 16) * GA_ROW_B +
                                                kk * 32) + a_lane;
                ldsm_x4(af[mi][0], af[mi][1], af[mi][2], af[mi][3], addr);
            }
#pragma unroll
            for (int nip = 0; nip < 4; nip++) {
                uint32_t addr = wb + (uint32_t)(kk * 16 * GW_ROW_B +
                                                (wn + nip * 16) * 2) + w_lane;
                uint32_t r0, r1, r2, r3;
                ldsm_x4_t(r0, r1, r2, r3, addr);
                mma_f16(acc[0][2 * nip],     af[0], r0, r1);
                mma_f16(acc[1][2 * nip],     af[1], r0, r1);
                mma_f16(acc[0][2 * nip + 1], af[0], r2, r3);
                mma_f16(acc[1][2 * nip + 1], af[1], r2, r3);
            }
        }
        __syncthreads();
    }
#undef G_ISSUE

    // epilogue: bias, (Q: scale), fp16 pack, store
    const float qs = (zi == 0) ? 0.125f * 1.4426950408889634f : 1.0f;
    __half* dst = (zi == 0) ? g_Qh : (zi == 1) ? g_Kh : g_Vh;
#pragma unroll
    for (int ni = 0; ni < 8; ni++) {
        int col = n0 + wn + ni * 8 + 2 * tig;
        float b0 = bias[col], b1 = bias[col + 1];
#pragma unroll
        for (int mi = 0; mi < 2; mi++) {
            int row = m0 + wm + mi * 16 + g;
            *(uint32_t*)&dst[row * DIM + col] =
                packh2((acc[mi][ni][1] + b1) * qs, (acc[mi][ni][0] + b0) * qs);
            *(uint32_t*)&dst[(row + 8) * DIM + col] =
                packh2((acc[mi][ni][3] + b1) * qs, (acc[mi][ni][2] + b0) * qs);
        }
    }
}

// ---------------------------------------------------------------------------
// Flash attention, fp16 m16n8k16, m32 warp tile, 3-stage cp.async pipeline.
// K and V both in natural [s][d] fp16 layout; K fragments via ldmatrix,
// V fragments via ldmatrix.trans; P packs directly from S C-fragments
// (fp16x2 == A-fragment layout, no permutation, no shuffles).
// Grid (SEQ/128, NH), block 128 = 4 warps (warp w: Q rows w*32..+31).
// ---------------------------------------------------------------------------
#define KST_B 144                          // 64 halves + pad, bytes
#define TILE_B (64 * KST_B)                // 9216
#define STG_B (2 * TILE_B)                 // 18432
#define ATTN_SMEM (3 * STG_B)              // 55296

__global__ __launch_bounds__(128, 2) void attn_f16(float* __restrict__ out)
{
    extern __shared__ uint8_t smem_dyn[];
    const uint32_t sbase = (uint32_t)__cvta_generic_to_shared(smem_dyn);

    const int tid  = threadIdx.x;
    const int lane = tid & 31;
    const int w    = tid >> 5;
    const int g    = lane >> 2;
    const int tig  = lane & 3;
    const int h    = blockIdx.y;
    const int rowbase = blockIdx.x * 128 + w * 32;
    const int hh = h * HD;

    const int lrow = lane & 7;
    const int lmat = lane >> 3;
    const uint32_t lane_k = (uint32_t)(lrow * KST_B + lmat * 16);
    const uint32_t lane_v = (uint32_t)((lmat * 8 + lrow) * KST_B);

#define A_ISSUE(BUF, KT)                                                      \
    {                                                                         \
        uint32_t kb = sbase + (BUF) * STG_B;                                  \
        uint32_t vb = kb + TILE_B;                                            \
        _Pragma("unroll")                                                     \
        for (int it = 0; it < 4; it++) {                                      \
            int id = tid + it * 128;                                          \
            int r = id >> 3, j = id & 7;                                      \
            uint32_t off = (uint32_t)(r * KST_B + j * 16);                    \
            cp16(kb + off, &g_Kh[((KT) * 64 + r) * DIM + hh + j * 8]);        \
            cp16(vb + off, &g_Vh[((KT) * 64 + r) * DIM + hh + j * 8]);        \
        }                                                                     \
        cp_commit();                                                          \
    }

    A_ISSUE(0, 0);
    A_ISSUE(1, 1);

    // Q fragments (fp16, pre-scaled in GEMM): qa[t][kfp][0..3]
    uint32_t qa[2][4][4];
#pragma unroll
    for (int t = 0; t < 2; t++)
#pragma unroll
        for (int kfp = 0; kfp < 4; kfp++) {
            const __half* q0 = &g_Qh[(rowbase + t * 16 + g) * DIM + hh + kfp * 16];
            const __half* q1 = q0 + 8 * DIM;
            qa[t][kfp][0] = *(const uint32_t*)&q0[2 * tig];
            qa[t][kfp][1] = *(const uint32_t*)&q1[2 * tig];
            qa[t][kfp][2] = *(const uint32_t*)&q0[8 + 2 * tig];
            qa[t][kfp][3] = *(const uint32_t*)&q1[8 + 2 * tig];
        }

    float o[2][8][4];
#pragma unroll
    for (int t = 0; t < 2; t++)
#pragma unroll
        for (int nf = 0; nf < 8; nf++)
#pragma unroll
            for (int c = 0; c < 4; c++) o[t][nf][c] = 0.f;
    float m_[4] = {-1e30f, -1e30f, -1e30f, -1e30f};
    float l_[4] = {0.f, 0.f, 0.f, 0.f};

    int buf = 0;
    for (int kt = 0; kt < NT; kt++) {
        if (kt + 1 < NT) cp_wait<1>(); else cp_wait<0>();
        __syncthreads();

        if (kt + 2 < NT) {
            int nb = buf + 2; if (nb >= 3) nb -= 3;
            A_ISSUE(nb, kt + 2);
        }

        const uint32_t kstage = sbase + buf * STG_B;
        const uint32_t vstage = kstage + TILE_B;

        // ---- S = Qs @ K^T (fp16 k16), both m16 tiles share every B frag ----
        float s[2][8][4];
#pragma unroll
        for (int nf = 0; nf < 8; nf++) {
            s[0][nf][0] = s[0][nf][1] = s[0][nf][2] = s[0][nf][3] = 0.f;
            s[1][nf][0] = s[1][nf][1] = s[1][nf][2] = s[1][nf][3] = 0.f;
            uint32_t a = kstage + (uint32_t)(nf * 8 * KST_B) + lane_k;
            uint32_t b0, b1, b2, b3;
            ldsm_x4(b0, b1, b2, b3, a);          // d segs 0..3 -> kfp 0,1
            mma_f16(s[0][nf], qa[0][0], b0, b1);
            mma_f16(s[1][nf], qa[1][0], b0, b1);
            mma_f16(s[0][nf], qa[0][1], b2, b3);
            mma_f16(s[1][nf], qa[1][1], b2, b3);
            ldsm_x4(b0, b1, b2, b3, a + 64);     // d segs 4..7 -> kfp 2,3
            mma_f16(s[0][nf], qa[0][2], b0, b1);
            mma_f16(s[1][nf], qa[1][2], b0, b1);
            mma_f16(s[0][nf], qa[0][3], b2, b3);
            mma_f16(s[1][nf], qa[1][3], b2, b3);
        }

        // ---- online softmax (base 2; scale baked into Q) ----
        uint32_t p[2][4][4];
#pragma unroll
        for (int t = 0; t < 2; t++) {
            float mx0 = -1e30f, mx1 = -1e30f;
#pragma unroll
            for (int nf = 0; nf < 8; nf++) {
                mx0 = fmaxf(mx0, fmaxf(s[t][nf][0], s[t][nf][1]));
                mx1 = fmaxf(mx1, fmaxf(s[t][nf][2], s[t][nf][3]));
            }
            mx0 = fmaxf(mx0, __shfl_xor_sync(0xffffffffu, mx0, 1));
            mx0 = fmaxf(mx0, __shfl_xor_sync(0xffffffffu, mx0, 2));
            mx1 = fmaxf(mx1, __shfl_xor_sync(0xffffffffu, mx1, 1));
            mx1 = fmaxf(mx1, __shfl_xor_sync(0xffffffffu, mx1, 2));
            float mn0 = fmaxf(m_[2 * t],     mx0);
            float mn1 = fmaxf(m_[2 * t + 1], mx1);
            float a0 = ex2f(m_[2 * t]     - mn0);
            float a1 = ex2f(m_[2 * t + 1] - mn1);
            m_[2 * t] = mn0; m_[2 * t + 1] = mn1;
            l_[2 * t] *= a0; l_[2 * t + 1] *= a1;
#pragma unroll
            for (int nf = 0; nf < 8; nf++) {
                o[t][nf][0] *= a0; o[t][nf][1] *= a0;
                o[t][nf][2] *= a1; o[t][nf][3] *= a1;
            }
            float rs0 = 0.f, rs1 = 0.f;
#pragma unroll
            for (int nf = 0; nf < 8; nf++) {
                float e0 = ex2f(s[t][nf][0] - mn0);
                float e1 = ex2f(s[t][nf][1] - mn0);
                float e2 = ex2f(s[t][nf][2] - mn1);
                float e3 = ex2f(s[t][nf][3] - mn1);
                rs0 += e0 + e1;
                rs1 += e2 + e3;
                s[t][nf][0] = e0; s[t][nf][1] = e1;
                s[t][nf][2] = e2; s[t][nf][3] = e3;
            }
            rs0 += __shfl_xor_sync(0xffffffffu, rs0, 1);
            rs0 += __shfl_xor_sync(0xffffffffu, rs0, 2);
            rs1 += __shfl_xor_sync(0xffffffffu, rs1, 1);
            rs1 += __shfl_xor_sync(0xffffffffu, rs1, 2);
            l_[2 * t] += rs0; l_[2 * t + 1] += rs1;

            // pack P: C-fragment pairs are exactly the k16 A-fragment halves
#pragma unroll
            for (int kfp = 0; kfp < 4; kfp++) {
                p[t][kfp][0] = packh2(s[t][2 * kfp][1],     s[t][2 * kfp][0]);
                p[t][kfp][1] = packh2(s[t][2 * kfp][3],     s[t][2 * kfp][2]);
                p[t][kfp][2] = packh2(s[t][2 * kfp + 1][1], s[t][2 * kfp + 1][0]);
                p[t][kfp][3] = packh2(s[t][2 * kfp + 1][3], s[t][2 * kfp + 1][2]);
            }
        }

        // ---- O += P @ V (V natural layout, ldmatrix.trans B fragments) ----
#pragma unroll
        for (int nf = 0; nf < 8; nf++) {
            uint32_t a = vstage + (uint32_t)(nf * 16) + lane_v;
            uint32_t v0, v1, v2, v3;
            ldsm_x4_t(v0, v1, v2, v3, a);            // kv blocks 0..3 -> kfp 0,1
            mma_f16(o[0][nf], p[0][0], v0, v1);
            mma_f16(o[1][nf], p[1][0], v0, v1);
            mma_f16(o[0][nf], p[0][1], v2, v3);
            mma_f16(o[1][nf], p[1][1], v2, v3);
            ldsm_x4_t(v0, v1, v2, v3, a + 32 * KST_B);  // kv 32..63 -> kfp 2,3
            mma_f16(o[0][nf], p[0][2], v0, v1);
            mma_f16(o[1][nf], p[1][2], v0, v1);
            mma_f16(o[0][nf], p[0][3], v2, v3);
            mma_f16(o[1][nf], p[1][3], v2, v3);
        }

        buf++; if (buf >= 3) buf = 0;
    }
#undef A_ISSUE

    // ---- normalize + store ----
#pragma unroll
    for (int t = 0; t < 2; t++) {
        float inv0 = 1.0f / l_[2 * t];
        float inv1 = 1.0f / l_[2 * t + 1];
#pragma unroll
        for (int nf = 0; nf < 8; nf++) {
            int col = hh + nf * 8 + 2 * tig;
            float2 v0 = make_float2(o[t][nf][0] * inv0, o[t][nf][1] * inv0);
            float2 v1 = make_float2(o[t][nf][2] * inv1, o[t][nf][3] * inv1);
            *(float2*)&out[(rowbase + t * 16 + g) * DIM + col]     = v0;
            *(float2*)&out[(rowbase + t * 16 + g + 8) * DIM + col] = v1;
        }
    }
}

extern "C" void kernel_launch(void* const* d_in, const int* in_sizes, int n_in,
                              void* d_out, int out_size)
{
    const float* hs = (const float*)d_in[0];
    const float* Wq = (const float*)d_in[1];
    const float* bq = (const float*)d_in[2];
    const float* Wk = (const float*)d_in[3];
    const float* bk = (const float*)d_in[4];
    const float* Wv = (const float*)d_in[5];
    const float* bv = (const float*)d_in[6];
    float* out = (float*)d_out;

    cudaFuncSetAttribute(attn_f16,
                         cudaFuncAttributeMaxDynamicSharedMemorySize,
                         ATTN_SMEM);

    dim3 g_cvt(SEQ * DIM / 4 / 256, 1, 4);
    cvt_fp16<<<g_cvt, 256>>>(hs, Wq, Wk, Wv);

    dim3 g_gemm(DIM / 128, SEQ / 128, 3);
    qkv_gemm_f16<<<g_gemm, 256>>>(bq, bk, bv);

    dim3 g_attn(SEQ / 128, NH);
    attn_f16<<<g_attn, 128, ATTN_SMEM>>>(out);
}